// round 1
// baseline (speedup 1.0000x reference)
#include <cuda_runtime.h>
#include <math.h>

// Problem constants (B=2, S=2048, D=2048, H=16, HD=128)
#define S_LEN 2048
#define DMODEL 2048
#define NH 16
#define HDIM 128
#define BATCH 2
#define NTOK (BATCH * S_LEN)   // 4096

// Scratch (allocation-free rule: __device__ globals)
__device__ float g_Q[(size_t)NTOK * DMODEL];
__device__ float g_K[(size_t)NTOK * DMODEL];
__device__ float g_V[(size_t)NTOK * DMODEL];
__device__ float g_AO[(size_t)NTOK * DMODEL];

// ---------------------------------------------------------------------------
// SGEMM: C[M,N] = A[M,K] @ B[K,N], row-major. M%128==0, N%128==0, K%16==0.
// 128x128 block tile, BK=16, 256 threads, 8x8 per thread.
// ---------------------------------------------------------------------------
__global__ void __launch_bounds__(256) sgemm_kernel(
    const float* __restrict__ A, const float* __restrict__ B,
    float* __restrict__ C, int M, int N, int K)
{
    __shared__ float As[16][128];
    __shared__ float Bs[16][128];

    const int tid = threadIdx.x;
    const int tx = tid & 15;
    const int ty = tid >> 4;
    const int row0 = blockIdx.y * 128;
    const int col0 = blockIdx.x * 128;

    const int arow = tid >> 2;          // 0..63
    const int acol = (tid & 3) * 4;     // 0,4,8,12
    const int brow = tid >> 5;          // 0..7
    const int bcol = (tid & 31) * 4;    // 0..124

    const float* Ap  = A + (size_t)(row0 + arow) * K + acol;
    const float* Ap2 = A + (size_t)(row0 + arow + 64) * K + acol;
    const float* Bp  = B + (size_t)brow * N + col0 + bcol;
    const float* Bp2 = B + (size_t)(brow + 8) * N + col0 + bcol;

    float acc[8][8];
#pragma unroll
    for (int i = 0; i < 8; ++i)
#pragma unroll
        for (int j = 0; j < 8; ++j) acc[i][j] = 0.0f;

    for (int kt = 0; kt < K; kt += 16) {
        float4 a0 = *(const float4*)(Ap + kt);
        float4 a1 = *(const float4*)(Ap2 + kt);
        float4 b0 = *(const float4*)(Bp + (size_t)kt * N);
        float4 b1 = *(const float4*)(Bp2 + (size_t)kt * N);

        __syncthreads();
        As[acol + 0][arow] = a0.x;
        As[acol + 1][arow] = a0.y;
        As[acol + 2][arow] = a0.z;
        As[acol + 3][arow] = a0.w;
        As[acol + 0][arow + 64] = a1.x;
        As[acol + 1][arow + 64] = a1.y;
        As[acol + 2][arow + 64] = a1.z;
        As[acol + 3][arow + 64] = a1.w;
        *(float4*)&Bs[brow][bcol]     = b0;
        *(float4*)&Bs[brow + 8][bcol] = b1;
        __syncthreads();

#pragma unroll
        for (int k = 0; k < 16; ++k) {
            float av[8], bv[8];
            *(float4*)&av[0] = *(const float4*)&As[k][ty * 8];
            *(float4*)&av[4] = *(const float4*)&As[k][ty * 8 + 4];
            *(float4*)&bv[0] = *(const float4*)&Bs[k][tx * 8];
            *(float4*)&bv[4] = *(const float4*)&Bs[k][tx * 8 + 4];
#pragma unroll
            for (int i = 0; i < 8; ++i)
#pragma unroll
                for (int j = 0; j < 8; ++j)
                    acc[i][j] = fmaf(av[i], bv[j], acc[i][j]);
        }
    }

#pragma unroll
    for (int i = 0; i < 8; ++i) {
        float* Cp = C + (size_t)(row0 + ty * 8 + i) * N + col0 + tx * 8;
        *(float4*)Cp       = make_float4(acc[i][0], acc[i][1], acc[i][2], acc[i][3]);
        *(float4*)(Cp + 4) = make_float4(acc[i][4], acc[i][5], acc[i][6], acc[i][7]);
    }
}

// ---------------------------------------------------------------------------
// RoPE: applied to Q and K in place. One thread per (token, head, j<64).
// ---------------------------------------------------------------------------
__global__ void __launch_bounds__(256) rope_kernel(float* __restrict__ Q,
                                                   float* __restrict__ K)
{
    const int idx = blockIdx.x * blockDim.x + threadIdx.x;
    const int total = NTOK * NH * (HDIM / 2);
    if (idx >= total) return;

    const int j = idx & 63;
    const int h = (idx >> 6) & (NH - 1);
    const int t = idx >> 10;
    const int pos = t & (S_LEN - 1);

    // inv_freq = 10000^(-j/64); compute in double to keep angle error at the
    // fp32-ulp floor (matches the reference's intrinsic precision).
    const double inv = exp(-(double)j * (9.210340371976184 / 64.0));
    const float ang = (float)((double)pos * inv);
    float sn, cs;
    sincosf(ang, &sn, &cs);

    const size_t base = (size_t)t * DMODEL + (size_t)h * HDIM + j;
    const float q1 = Q[base], q2 = Q[base + 64];
    Q[base]      = q1 * cs - q2 * sn;
    Q[base + 64] = q2 * cs + q1 * sn;
    const float k1 = K[base], k2 = K[base + 64];
    K[base]      = k1 * cs - k2 * sn;
    K[base + 64] = k2 * cs + k1 * sn;
}

// ---------------------------------------------------------------------------
// Flash attention (causal, tanh-cap 50, attention sink logit 0).
// Per block: one (batch, head, 64-row Q tile). 256 threads (tx=0..15, ty=0..15).
// S tile 64x64: thread owns rows {ty*4+i}, cols {tx + 16*j}.
// O tile 64x128: thread owns rows {ty*4+i}, cols {tx*8 .. tx*8+7}.
// ---------------------------------------------------------------------------
#define BQ 64
#define BKV 64
#define QS_STRIDE 128
#define KS_STRIDE 132   // padded: Ks reads are ~2-way instead of 16-way conflicted
#define VS_STRIDE 128
#define PS_STRIDE 68
#define FLASH_SMEM ((BQ*QS_STRIDE + BKV*KS_STRIDE + BKV*VS_STRIDE + BQ*PS_STRIDE) * 4)

__global__ void __launch_bounds__(256, 1) flash_kernel(
    const float* __restrict__ Q, const float* __restrict__ K,
    const float* __restrict__ V, float* __restrict__ O)
{
    extern __shared__ float sm[];
    float* Qs = sm;                               // 64 x 128
    float* Ks = Qs + BQ * QS_STRIDE;              // 64 x 132
    float* Vs = Ks + BKV * KS_STRIDE;             // 64 x 128
    float* Ps = Vs + BKV * VS_STRIDE;             // 64 x 68

    const int qb = gridDim.x - 1 - blockIdx.x;    // long blocks first
    const int h = blockIdx.y;
    const int b = blockIdx.z;
    const int tid = threadIdx.x;
    const int tx = tid & 15;
    const int ty = tid >> 4;
    const int q0 = qb * BQ;

    const float SCALE = 0.08838834764831845f;     // 1/sqrt(128)
    const float CAP = 50.0f;
    const float INV_CAP = 1.0f / 50.0f;

    const size_t hb = (size_t)b * S_LEN * DMODEL + (size_t)h * HDIM;
    const float* Qg = Q + hb;
    const float* Kg = K + hb;
    const float* Vg = V + hb;

    // Load Q tile
    for (int i = tid; i < BQ * HDIM / 4; i += 256) {
        const int r = i >> 5;
        const int c = (i & 31) * 4;
        *(float4*)&Qs[r * QS_STRIDE + c] =
            *(const float4*)&Qg[(size_t)(q0 + r) * DMODEL + c];
    }

    float acc[4][8];
#pragma unroll
    for (int i = 0; i < 4; ++i)
#pragma unroll
        for (int j = 0; j < 8; ++j) acc[i][j] = 0.0f;

    float m_i[4] = {0.0f, 0.0f, 0.0f, 0.0f};      // sink: max(scores, 0)
    float l_i[4] = {1.0f, 1.0f, 1.0f, 1.0f};      // sink: + exp(0 - m)

    for (int kb = 0; kb <= qb; ++kb) {
        __syncthreads();
        const int k0 = kb * BKV;
        for (int i = tid; i < BKV * HDIM / 4; i += 256) {
            const int r = i >> 5;
            const int c = (i & 31) * 4;
            *(float4*)&Ks[r * KS_STRIDE + c] =
                *(const float4*)&Kg[(size_t)(k0 + r) * DMODEL + c];
            *(float4*)&Vs[r * VS_STRIDE + c] =
                *(const float4*)&Vg[(size_t)(k0 + r) * DMODEL + c];
        }
        __syncthreads();

        // S = Q @ K^T   (64x64 over HD=128)
        float s[4][4];
#pragma unroll
        for (int i = 0; i < 4; ++i)
#pragma unroll
            for (int j = 0; j < 4; ++j) s[i][j] = 0.0f;

#pragma unroll 8
        for (int k = 0; k < HDIM; k += 4) {
            float4 qv[4], kv[4];
#pragma unroll
            for (int i = 0; i < 4; ++i)
                qv[i] = *(const float4*)&Qs[(ty * 4 + i) * QS_STRIDE + k];
#pragma unroll
            for (int j = 0; j < 4; ++j)
                kv[j] = *(const float4*)&Ks[(tx + 16 * j) * KS_STRIDE + k];
#pragma unroll
            for (int i = 0; i < 4; ++i)
#pragma unroll
                for (int j = 0; j < 4; ++j) {
                    s[i][j] = fmaf(qv[i].x, kv[j].x, s[i][j]);
                    s[i][j] = fmaf(qv[i].y, kv[j].y, s[i][j]);
                    s[i][j] = fmaf(qv[i].z, kv[j].z, s[i][j]);
                    s[i][j] = fmaf(qv[i].w, kv[j].w, s[i][j]);
                }
        }

        const bool diag = (kb == qb);
#pragma unroll
        for (int i = 0; i < 4; ++i) {
            const int qidx = q0 + ty * 4 + i;
            float sv[4];
            float mrow = -3.4e38f;
#pragma unroll
            for (int j = 0; j < 4; ++j) {
                float v = s[i][j] * SCALE;
                v = CAP * tanhf(v * INV_CAP);     // cap BEFORE mask (ref order)
                if (diag && (k0 + tx + 16 * j) > qidx) v = -INFINITY;
                sv[j] = v;
                mrow = fmaxf(mrow, v);
            }
#pragma unroll
            for (int w = 1; w < 16; w <<= 1)
                mrow = fmaxf(mrow, __shfl_xor_sync(0xffffffffu, mrow, w));

            const float mnew = fmaxf(m_i[i], mrow);
            const float corr = __expf(m_i[i] - mnew);
            m_i[i] = mnew;

            float rs = 0.0f;
#pragma unroll
            for (int j = 0; j < 4; ++j) {
                const float p = __expf(sv[j] - mnew);
                Ps[(ty * 4 + i) * PS_STRIDE + tx + 16 * j] = p;
                rs += p;
            }
#pragma unroll
            for (int w = 1; w < 16; w <<= 1)
                rs += __shfl_xor_sync(0xffffffffu, rs, w);

            l_i[i] = l_i[i] * corr + rs;
#pragma unroll
            for (int j = 0; j < 8; ++j) acc[i][j] *= corr;
        }
        __syncthreads();

        // O += P @ V
#pragma unroll 4
        for (int k = 0; k < BKV; k += 4) {
            float4 pv[4];
#pragma unroll
            for (int i = 0; i < 4; ++i)
                pv[i] = *(const float4*)&Ps[(ty * 4 + i) * PS_STRIDE + k];
#pragma unroll
            for (int kk = 0; kk < 4; ++kk) {
                const float4 v0 = *(const float4*)&Vs[(k + kk) * VS_STRIDE + tx * 8];
                const float4 v1 = *(const float4*)&Vs[(k + kk) * VS_STRIDE + tx * 8 + 4];
#pragma unroll
                for (int i = 0; i < 4; ++i) {
                    const float p = (kk == 0) ? pv[i].x :
                                    (kk == 1) ? pv[i].y :
                                    (kk == 2) ? pv[i].z : pv[i].w;
                    acc[i][0] = fmaf(p, v0.x, acc[i][0]);
                    acc[i][1] = fmaf(p, v0.y, acc[i][1]);
                    acc[i][2] = fmaf(p, v0.z, acc[i][2]);
                    acc[i][3] = fmaf(p, v0.w, acc[i][3]);
                    acc[i][4] = fmaf(p, v1.x, acc[i][4]);
                    acc[i][5] = fmaf(p, v1.y, acc[i][5]);
                    acc[i][6] = fmaf(p, v1.z, acc[i][6]);
                    acc[i][7] = fmaf(p, v1.w, acc[i][7]);
                }
            }
        }
    }

    // Epilogue: normalize and store
    float* Og = O + hb;
#pragma unroll
    for (int i = 0; i < 4; ++i) {
        const float inv = 1.0f / l_i[i];
        const int r = q0 + ty * 4 + i;
        float* Op = Og + (size_t)r * DMODEL + tx * 8;
        *(float4*)Op = make_float4(acc[i][0] * inv, acc[i][1] * inv,
                                   acc[i][2] * inv, acc[i][3] * inv);
        *(float4*)(Op + 4) = make_float4(acc[i][4] * inv, acc[i][5] * inv,
                                         acc[i][6] * inv, acc[i][7] * inv);
    }
}

// ---------------------------------------------------------------------------
extern "C" void kernel_launch(void* const* d_in, const int* in_sizes, int n_in,
                              void* d_out, int out_size)
{
    const float* x  = (const float*)d_in[0];
    const float* Wq = (const float*)d_in[1];
    const float* Wk = (const float*)d_in[2];
    const float* Wv = (const float*)d_in[3];
    const float* Wo = (const float*)d_in[4];
    float* out = (float*)d_out;

    float *Qp, *Kp, *Vp, *AOp;
    cudaGetSymbolAddress((void**)&Qp,  g_Q);
    cudaGetSymbolAddress((void**)&Kp,  g_K);
    cudaGetSymbolAddress((void**)&Vp,  g_V);
    cudaGetSymbolAddress((void**)&AOp, g_AO);

    cudaFuncSetAttribute(flash_kernel,
                         cudaFuncAttributeMaxDynamicSharedMemorySize,
                         FLASH_SMEM);

    const dim3 gg(DMODEL / 128, NTOK / 128);   // (16, 32)

    sgemm_kernel<<<gg, 256>>>(x, Wq, Qp, NTOK, DMODEL, DMODEL);
    sgemm_kernel<<<gg, 256>>>(x, Wk, Kp, NTOK, DMODEL, DMODEL);
    sgemm_kernel<<<gg, 256>>>(x, Wv, Vp, NTOK, DMODEL, DMODEL);

    const int nrope = NTOK * NH * (HDIM / 2);
    rope_kernel<<<nrope / 256, 256>>>(Qp, Kp);

    const dim3 gf(S_LEN / BQ, NH, BATCH);      // (32, 16, 2)
    flash_kernel<<<gf, 256, FLASH_SMEM>>>(Qp, Kp, Vp, AOp);

    sgemm_kernel<<<gg, 256>>>(AOp, Wo, out, NTOK, DMODEL, DMODEL);
}

// round 2
// speedup vs baseline: 1.7140x; 1.7140x over previous
#include <cuda_runtime.h>
#include <math.h>
#include <stdint.h>

// Problem constants (B=2, S=2048, D=2048, H=16, HD=128)
#define S_LEN 2048
#define DMODEL 2048
#define NH 16
#define HDIM 128
#define BATCH 2
#define NTOK (BATCH * S_LEN)   // 4096

// Scratch (allocation-free rule: __device__ globals)
__device__ float g_Q[(size_t)NTOK * DMODEL];
__device__ float g_K[(size_t)NTOK * DMODEL];
__device__ float g_V[(size_t)NTOK * DMODEL];
__device__ float g_AO[(size_t)NTOK * DMODEL];

// ---------------------------------------------------------------------------
// TF32 tensor-core GEMM: C[M,N] = A[M,K] @ B[K,N], row-major fp32 in/out.
// Block tile 128x128x32, 256 threads (8 warps in 2x4 grid), warp tile 64x32.
// mma.sync.aligned.m16n8k8 tf32. Conflict-free smem (strides 36 / 132).
// ---------------------------------------------------------------------------
__device__ __forceinline__ uint32_t f2tf32(float f) {
    uint32_t r;
    asm("cvt.rna.tf32.f32 %0, %1;" : "=r"(r) : "f"(f));
    return r;
}

__device__ __forceinline__ void mma_tf32(float* c, const uint32_t* a,
                                         const uint32_t* b) {
    asm volatile(
        "mma.sync.aligned.m16n8k8.row.col.f32.tf32.tf32.f32 "
        "{%0,%1,%2,%3}, {%4,%5,%6,%7}, {%8,%9}, {%0,%1,%2,%3};"
        : "+f"(c[0]), "+f"(c[1]), "+f"(c[2]), "+f"(c[3])
        : "r"(a[0]), "r"(a[1]), "r"(a[2]), "r"(a[3]), "r"(b[0]), "r"(b[1]));
}

#define AS_STRIDE 36    // (m*36 + k) % 32 = (4m+k)%32 -> conflict-free frag loads
#define BS_STRIDE 132   // (k*132 + n) % 32 = (4k+n)%32 -> conflict-free frag loads

__global__ void __launch_bounds__(256) tf32_gemm_kernel(
    const float* __restrict__ A, const float* __restrict__ B,
    float* __restrict__ C, int M, int N, int K)
{
    __shared__ uint32_t As[128][AS_STRIDE];   // [m][k]
    __shared__ uint32_t Bs[32][BS_STRIDE];    // [k][n]

    const int tid = threadIdx.x;
    const int wid = tid >> 5;
    const int lane = tid & 31;
    const int g = lane >> 2;          // groupID 0..7
    const int tig = lane & 3;         // thread-in-group 0..3

    const int warp_m = wid >> 2;      // 0..1
    const int warp_n = wid & 3;       // 0..3
    const int m0w = warp_m * 64;
    const int n0w = warp_n * 32;

    const int row0 = blockIdx.y * 128;
    const int col0 = blockIdx.x * 128;

    // Global-load assignments
    const int ar  = tid >> 3;         // 0..31 (A row within pass)
    const int ac4 = (tid & 7) * 4;    // A col (0..28 step 4)
    const int br  = tid >> 5;         // 0..7  (B row within pass)
    const int bc4 = (tid & 31) * 4;   // B col (0..124 step 4)

    const int ntiles = K >> 5;        // K/32

    float4 areg[4], breg[4];

    // Prologue: load tile 0
#pragma unroll
    for (int p = 0; p < 4; ++p) {
        areg[p] = *(const float4*)&A[(size_t)(row0 + ar + 32 * p) * K + ac4];
        breg[p] = *(const float4*)&B[(size_t)(br + 8 * p) * N + col0 + bc4];
    }
#pragma unroll
    for (int p = 0; p < 4; ++p) {
        const int r = ar + 32 * p;
        As[r][ac4 + 0] = f2tf32(areg[p].x);
        As[r][ac4 + 1] = f2tf32(areg[p].y);
        As[r][ac4 + 2] = f2tf32(areg[p].z);
        As[r][ac4 + 3] = f2tf32(areg[p].w);
        const int kr = br + 8 * p;
        Bs[kr][bc4 + 0] = f2tf32(breg[p].x);
        Bs[kr][bc4 + 1] = f2tf32(breg[p].y);
        Bs[kr][bc4 + 2] = f2tf32(breg[p].z);
        Bs[kr][bc4 + 3] = f2tf32(breg[p].w);
    }
    __syncthreads();

    float acc[4][4][4];
#pragma unroll
    for (int mt = 0; mt < 4; ++mt)
#pragma unroll
        for (int nt = 0; nt < 4; ++nt)
#pragma unroll
            for (int r = 0; r < 4; ++r) acc[mt][nt][r] = 0.0f;

    for (int kt = 0; kt < ntiles; ++kt) {
        // Prefetch next tile into registers (overlaps with MMA)
        if (kt + 1 < ntiles) {
            const int ka = (kt + 1) * 32;
#pragma unroll
            for (int p = 0; p < 4; ++p) {
                areg[p] = *(const float4*)&A[(size_t)(row0 + ar + 32 * p) * K + ka + ac4];
                breg[p] = *(const float4*)&B[(size_t)(ka + br + 8 * p) * N + col0 + bc4];
            }
        }

        // Compute on the tile currently in smem
#pragma unroll
        for (int ks = 0; ks < 4; ++ks) {
            const int k0 = ks * 8;
            uint32_t af[4][4];
            uint32_t bf[4][2];
#pragma unroll
            for (int mt = 0; mt < 4; ++mt) {
                const int r = m0w + mt * 16 + g;
                af[mt][0] = As[r][k0 + tig];
                af[mt][1] = As[r + 8][k0 + tig];
                af[mt][2] = As[r][k0 + tig + 4];
                af[mt][3] = As[r + 8][k0 + tig + 4];
            }
#pragma unroll
            for (int nt = 0; nt < 4; ++nt) {
                const int c = n0w + nt * 8 + g;
                bf[nt][0] = Bs[k0 + tig][c];
                bf[nt][1] = Bs[k0 + tig + 4][c];
            }
#pragma unroll
            for (int mt = 0; mt < 4; ++mt)
#pragma unroll
                for (int nt = 0; nt < 4; ++nt)
                    mma_tf32(acc[mt][nt], af[mt], bf[nt]);
        }

        __syncthreads();
        if (kt + 1 < ntiles) {
#pragma unroll
            for (int p = 0; p < 4; ++p) {
                const int r = ar + 32 * p;
                As[r][ac4 + 0] = f2tf32(areg[p].x);
                As[r][ac4 + 1] = f2tf32(areg[p].y);
                As[r][ac4 + 2] = f2tf32(areg[p].z);
                As[r][ac4 + 3] = f2tf32(areg[p].w);
                const int kr = br + 8 * p;
                Bs[kr][bc4 + 0] = f2tf32(breg[p].x);
                Bs[kr][bc4 + 1] = f2tf32(breg[p].y);
                Bs[kr][bc4 + 2] = f2tf32(breg[p].z);
                Bs[kr][bc4 + 3] = f2tf32(breg[p].w);
            }
            __syncthreads();
        }
    }

    // Epilogue: c0,c1 -> (row, 2tig..2tig+1); c2,c3 -> (row+8, same cols)
#pragma unroll
    for (int mt = 0; mt < 4; ++mt) {
        const int row = row0 + m0w + mt * 16 + g;
#pragma unroll
        for (int nt = 0; nt < 4; ++nt) {
            const int col = col0 + n0w + nt * 8 + 2 * tig;
            *(float2*)&C[(size_t)row * N + col] =
                make_float2(acc[mt][nt][0], acc[mt][nt][1]);
            *(float2*)&C[(size_t)(row + 8) * N + col] =
                make_float2(acc[mt][nt][2], acc[mt][nt][3]);
        }
    }
}

// ---------------------------------------------------------------------------
// RoPE: applied to Q and K in place. One thread per (token, head, j<64).
// ---------------------------------------------------------------------------
__global__ void __launch_bounds__(256) rope_kernel(float* __restrict__ Q,
                                                   float* __restrict__ K)
{
    const int idx = blockIdx.x * blockDim.x + threadIdx.x;
    const int total = NTOK * NH * (HDIM / 2);
    if (idx >= total) return;

    const int j = idx & 63;
    const int h = (idx >> 6) & (NH - 1);
    const int t = idx >> 10;
    const int pos = t & (S_LEN - 1);

    const double inv = exp(-(double)j * (9.210340371976184 / 64.0));
    const float ang = (float)((double)pos * inv);
    float sn, cs;
    sincosf(ang, &sn, &cs);

    const size_t base = (size_t)t * DMODEL + (size_t)h * HDIM + j;
    const float q1 = Q[base], q2 = Q[base + 64];
    Q[base]      = q1 * cs - q2 * sn;
    Q[base + 64] = q2 * cs + q1 * sn;
    const float k1 = K[base], k2 = K[base + 64];
    K[base]      = k1 * cs - k2 * sn;
    K[base + 64] = k2 * cs + k1 * sn;
}

// ---------------------------------------------------------------------------
// Flash attention (causal, tanh-cap 50, attention sink logit 0).
// Per block: one (batch, head, 64-row Q tile). 256 threads (tx=0..15, ty=0..15).
// ---------------------------------------------------------------------------
#define BQ 64
#define BKV 64
#define QS_STRIDE 128
#define KS_STRIDE 132
#define VS_STRIDE 128
#define PS_STRIDE 68
#define FLASH_SMEM ((BQ*QS_STRIDE + BKV*KS_STRIDE + BKV*VS_STRIDE + BQ*PS_STRIDE) * 4)

__global__ void __launch_bounds__(256, 1) flash_kernel(
    const float* __restrict__ Q, const float* __restrict__ K,
    const float* __restrict__ V, float* __restrict__ O)
{
    extern __shared__ float sm[];
    float* Qs = sm;                               // 64 x 128
    float* Ks = Qs + BQ * QS_STRIDE;              // 64 x 132
    float* Vs = Ks + BKV * KS_STRIDE;             // 64 x 128
    float* Ps = Vs + BKV * VS_STRIDE;             // 64 x 68

    const int qb = gridDim.x - 1 - blockIdx.x;    // long blocks first
    const int h = blockIdx.y;
    const int b = blockIdx.z;
    const int tid = threadIdx.x;
    const int tx = tid & 15;
    const int ty = tid >> 4;
    const int q0 = qb * BQ;

    const float SCALE = 0.08838834764831845f;     // 1/sqrt(128)
    const float CAP = 50.0f;
    const float INV_CAP = 1.0f / 50.0f;

    const size_t hb = (size_t)b * S_LEN * DMODEL + (size_t)h * HDIM;
    const float* Qg = Q + hb;
    const float* Kg = K + hb;
    const float* Vg = V + hb;

    for (int i = tid; i < BQ * HDIM / 4; i += 256) {
        const int r = i >> 5;
        const int c = (i & 31) * 4;
        *(float4*)&Qs[r * QS_STRIDE + c] =
            *(const float4*)&Qg[(size_t)(q0 + r) * DMODEL + c];
    }

    float acc[4][8];
#pragma unroll
    for (int i = 0; i < 4; ++i)
#pragma unroll
        for (int j = 0; j < 8; ++j) acc[i][j] = 0.0f;

    float m_i[4] = {0.0f, 0.0f, 0.0f, 0.0f};      // sink: max(scores, 0)
    float l_i[4] = {1.0f, 1.0f, 1.0f, 1.0f};      // sink: + exp(0 - m)

    for (int kb = 0; kb <= qb; ++kb) {
        __syncthreads();
        const int k0 = kb * BKV;
        for (int i = tid; i < BKV * HDIM / 4; i += 256) {
            const int r = i >> 5;
            const int c = (i & 31) * 4;
            *(float4*)&Ks[r * KS_STRIDE + c] =
                *(const float4*)&Kg[(size_t)(k0 + r) * DMODEL + c];
            *(float4*)&Vs[r * VS_STRIDE + c] =
                *(const float4*)&Vg[(size_t)(k0 + r) * DMODEL + c];
        }
        __syncthreads();

        float s[4][4];
#pragma unroll
        for (int i = 0; i < 4; ++i)
#pragma unroll
            for (int j = 0; j < 4; ++j) s[i][j] = 0.0f;

#pragma unroll 8
        for (int k = 0; k < HDIM; k += 4) {
            float4 qv[4], kv[4];
#pragma unroll
            for (int i = 0; i < 4; ++i)
                qv[i] = *(const float4*)&Qs[(ty * 4 + i) * QS_STRIDE + k];
#pragma unroll
            for (int j = 0; j < 4; ++j)
                kv[j] = *(const float4*)&Ks[(tx + 16 * j) * KS_STRIDE + k];
#pragma unroll
            for (int i = 0; i < 4; ++i)
#pragma unroll
                for (int j = 0; j < 4; ++j) {
                    s[i][j] = fmaf(qv[i].x, kv[j].x, s[i][j]);
                    s[i][j] = fmaf(qv[i].y, kv[j].y, s[i][j]);
                    s[i][j] = fmaf(qv[i].z, kv[j].z, s[i][j]);
                    s[i][j] = fmaf(qv[i].w, kv[j].w, s[i][j]);
                }
        }

        const bool diag = (kb == qb);
#pragma unroll
        for (int i = 0; i < 4; ++i) {
            const int qidx = q0 + ty * 4 + i;
            float sv[4];
            float mrow = -3.4e38f;
#pragma unroll
            for (int j = 0; j < 4; ++j) {
                float v = s[i][j] * SCALE;
                v = CAP * tanhf(v * INV_CAP);
                if (diag && (k0 + tx + 16 * j) > qidx) v = -INFINITY;
                sv[j] = v;
                mrow = fmaxf(mrow, v);
            }
#pragma unroll
            for (int w = 1; w < 16; w <<= 1)
                mrow = fmaxf(mrow, __shfl_xor_sync(0xffffffffu, mrow, w));

            const float mnew = fmaxf(m_i[i], mrow);
            const float corr = __expf(m_i[i] - mnew);
            m_i[i] = mnew;

            float rs = 0.0f;
#pragma unroll
            for (int j = 0; j < 4; ++j) {
                const float p = __expf(sv[j] - mnew);
                Ps[(ty * 4 + i) * PS_STRIDE + tx + 16 * j] = p;
                rs += p;
            }
#pragma unroll
            for (int w = 1; w < 16; w <<= 1)
                rs += __shfl_xor_sync(0xffffffffu, rs, w);

            l_i[i] = l_i[i] * corr + rs;
#pragma unroll
            for (int j = 0; j < 8; ++j) acc[i][j] *= corr;
        }
        __syncthreads();

#pragma unroll 4
        for (int k = 0; k < BKV; k += 4) {
            float4 pv[4];
#pragma unroll
            for (int i = 0; i < 4; ++i)
                pv[i] = *(const float4*)&Ps[(ty * 4 + i) * PS_STRIDE + k];
#pragma unroll
            for (int kk = 0; kk < 4; ++kk) {
                const float4 v0 = *(const float4*)&Vs[(k + kk) * VS_STRIDE + tx * 8];
                const float4 v1 = *(const float4*)&Vs[(k + kk) * VS_STRIDE + tx * 8 + 4];
#pragma unroll
                for (int i = 0; i < 4; ++i) {
                    const float p = (kk == 0) ? pv[i].x :
                                    (kk == 1) ? pv[i].y :
                                    (kk == 2) ? pv[i].z : pv[i].w;
                    acc[i][0] = fmaf(p, v0.x, acc[i][0]);
                    acc[i][1] = fmaf(p, v0.y, acc[i][1]);
                    acc[i][2] = fmaf(p, v0.z, acc[i][2]);
                    acc[i][3] = fmaf(p, v0.w, acc[i][3]);
                    acc[i][4] = fmaf(p, v1.x, acc[i][4]);
                    acc[i][5] = fmaf(p, v1.y, acc[i][5]);
                    acc[i][6] = fmaf(p, v1.z, acc[i][6]);
                    acc[i][7] = fmaf(p, v1.w, acc[i][7]);
                }
            }
        }
    }

    float* Og = O + hb;
#pragma unroll
    for (int i = 0; i < 4; ++i) {
        const float inv = 1.0f / l_i[i];
        const int r = q0 + ty * 4 + i;
        float* Op = Og + (size_t)r * DMODEL + tx * 8;
        *(float4*)Op = make_float4(acc[i][0] * inv, acc[i][1] * inv,
                                   acc[i][2] * inv, acc[i][3] * inv);
        *(float4*)(Op + 4) = make_float4(acc[i][4] * inv, acc[i][5] * inv,
                                         acc[i][6] * inv, acc[i][7] * inv);
    }
}

// ---------------------------------------------------------------------------
extern "C" void kernel_launch(void* const* d_in, const int* in_sizes, int n_in,
                              void* d_out, int out_size)
{
    const float* x  = (const float*)d_in[0];
    const float* Wq = (const float*)d_in[1];
    const float* Wk = (const float*)d_in[2];
    const float* Wv = (const float*)d_in[3];
    const float* Wo = (const float*)d_in[4];
    float* out = (float*)d_out;

    float *Qp, *Kp, *Vp, *AOp;
    cudaGetSymbolAddress((void**)&Qp,  g_Q);
    cudaGetSymbolAddress((void**)&Kp,  g_K);
    cudaGetSymbolAddress((void**)&Vp,  g_V);
    cudaGetSymbolAddress((void**)&AOp, g_AO);

    cudaFuncSetAttribute(flash_kernel,
                         cudaFuncAttributeMaxDynamicSharedMemorySize,
                         FLASH_SMEM);

    const dim3 gg(DMODEL / 128, NTOK / 128);   // (16, 32)

    tf32_gemm_kernel<<<gg, 256>>>(x, Wq, Qp, NTOK, DMODEL, DMODEL);
    tf32_gemm_kernel<<<gg, 256>>>(x, Wk, Kp, NTOK, DMODEL, DMODEL);
    tf32_gemm_kernel<<<gg, 256>>>(x, Wv, Vp, NTOK, DMODEL, DMODEL);

    const int nrope = NTOK * NH * (HDIM / 2);
    rope_kernel<<<nrope / 256, 256>>>(Qp, Kp);

    const dim3 gf(S_LEN / BQ, NH, BATCH);      // (32, 16, 2)
    flash_kernel<<<gf, 256, FLASH_SMEM>>>(Qp, Kp, Vp, AOp);

    tf32_gemm_kernel<<<gg, 256>>>(AOp, Wo, out, NTOK, DMODEL, DMODEL);
}

// round 3
// speedup vs baseline: 2.1448x; 1.2513x over previous
#include <cuda_runtime.h>
#include <cuda_bf16.h>
#include <math.h>
#include <stdint.h>

// Problem constants (B=2, S=2048, D=2048, H=16, HD=128)
#define S_LEN 2048
#define DMODEL 2048
#define NH 16
#define HDIM 128
#define BATCH 2
#define NTOK (BATCH * S_LEN)   // 4096

// ---------------------------------------------------------------------------
// Scratch (__device__ globals; allocation-free rule)
// ---------------------------------------------------------------------------
__device__ float g_Q[(size_t)NTOK * DMODEL];
__device__ float g_K[(size_t)NTOK * DMODEL];
__device__ float g_V[(size_t)NTOK * DMODEL];
__device__ float g_AO[(size_t)NTOK * DMODEL];

// bf16 hi/lo split operands
__device__ __nv_bfloat16 g_xh[(size_t)NTOK * DMODEL];
__device__ __nv_bfloat16 g_xl[(size_t)NTOK * DMODEL];
__device__ __nv_bfloat16 g_aoh[(size_t)NTOK * DMODEL];
__device__ __nv_bfloat16 g_aol[(size_t)NTOK * DMODEL];
// transposed weights [N][K], hi/lo
__device__ __nv_bfloat16 g_Wqh[(size_t)DMODEL * DMODEL];
__device__ __nv_bfloat16 g_Wql[(size_t)DMODEL * DMODEL];
__device__ __nv_bfloat16 g_Wkh[(size_t)DMODEL * DMODEL];
__device__ __nv_bfloat16 g_Wkl[(size_t)DMODEL * DMODEL];
__device__ __nv_bfloat16 g_Wvh[(size_t)DMODEL * DMODEL];
__device__ __nv_bfloat16 g_Wvl[(size_t)DMODEL * DMODEL];
__device__ __nv_bfloat16 g_Woh[(size_t)DMODEL * DMODEL];
__device__ __nv_bfloat16 g_Wol[(size_t)DMODEL * DMODEL];

// ---------------------------------------------------------------------------
// Helpers: bf16x2 pack / hi-lo split / mma
// ---------------------------------------------------------------------------
__device__ __forceinline__ uint32_t pack_bf16x2(float lo, float hi) {
    uint32_t r;
    asm("cvt.rn.bf16x2.f32 %0, %1, %2;" : "=r"(r) : "f"(hi), "f"(lo));
    return r;   // low halfword = lo
}

// split two fp32 into (hi bf16x2, lo bf16x2); lo = rn(x - float(hi))
__device__ __forceinline__ void split2(float a, float b,
                                       uint32_t& h, uint32_t& l) {
    h = pack_bf16x2(a, b);
    float ha = __uint_as_float(h << 16);
    float hb = __uint_as_float(h & 0xffff0000u);
    l = pack_bf16x2(a - ha, b - hb);
}

__device__ __forceinline__ void mma_bf16(float* c, const uint32_t* a,
                                         const uint32_t* b) {
    asm volatile(
        "mma.sync.aligned.m16n8k16.row.col.f32.bf16.bf16.f32 "
        "{%0,%1,%2,%3}, {%4,%5,%6,%7}, {%8,%9}, {%0,%1,%2,%3};"
        : "+f"(c[0]), "+f"(c[1]), "+f"(c[2]), "+f"(c[3])
        : "r"(a[0]), "r"(a[1]), "r"(a[2]), "r"(a[3]), "r"(b[0]), "r"(b[1]));
}

__device__ __forceinline__ uint32_t smem_u32(const void* p) {
    return (uint32_t)__cvta_generic_to_shared(p);
}
__device__ __forceinline__ void cp16(uint32_t dst, const void* src) {
    asm volatile("cp.async.cg.shared.global [%0], [%1], 16;"
                 :: "r"(dst), "l"(src));
}
__device__ __forceinline__ void cp_commit() {
    asm volatile("cp.async.commit_group;");
}
template <int N>
__device__ __forceinline__ void cp_wait() {
    asm volatile("cp.async.wait_group %0;" :: "n"(N));
}

// ---------------------------------------------------------------------------
// Pre-split kernels
// ---------------------------------------------------------------------------
// row-major fp32 -> hi/lo bf16 (same layout)
__global__ void __launch_bounds__(256) split_rows_kernel(
    const float* __restrict__ X, __nv_bfloat16* __restrict__ H,
    __nv_bfloat16* __restrict__ L, int n2)
{
    int i = blockIdx.x * blockDim.x + threadIdx.x;
    if (i >= n2) return;
    float2 v = ((const float2*)X)[i];
    uint32_t h, l;
    split2(v.x, v.y, h, l);
    ((uint32_t*)H)[i] = h;
    ((uint32_t*)L)[i] = l;
}

// W fp32 [K][N] -> transposed hi/lo bf16 [N][K]
__global__ void __launch_bounds__(256) split_transpose_kernel(
    const float* __restrict__ W, __nv_bfloat16* __restrict__ Th,
    __nv_bfloat16* __restrict__ Tl, int K, int N)
{
    __shared__ float t[32][33];
    const int k0 = blockIdx.x * 32;
    const int n0 = blockIdx.y * 32;
    const int tx = threadIdx.x & 31;
    const int ty = threadIdx.x >> 5;   // 0..7
#pragma unroll
    for (int i = 0; i < 4; ++i)
        t[ty + 8 * i][tx] = W[(size_t)(k0 + ty + 8 * i) * N + n0 + tx];
    __syncthreads();
#pragma unroll
    for (int i = 0; i < 4; ++i) {
        const int n = n0 + ty + 8 * i;
        const float v = t[tx][ty + 8 * i];   // element (k0+tx, n)
        __nv_bfloat16 h = __float2bfloat16_rn(v);
        __nv_bfloat16 l = __float2bfloat16_rn(v - __bfloat162float(h));
        Th[(size_t)n * K + k0 + tx] = h;
        Tl[(size_t)n * K + k0 + tx] = l;
    }
}

// ---------------------------------------------------------------------------
// bf16x3 GEMM: C[M,N] = (Ah+Al)[M,K] @ (Bth+Btl)^T, fp32 out.
// A hi/lo: [M][K] bf16 row-major. Bt hi/lo: [N][K] bf16 row-major.
// Block 128x128x32, 3-stage cp.async, 8 warps (2m x 4n), warp 64x32.
// smem word stride per row: 20 (16 data + 4 pad -> conflict-free frags).
// ---------------------------------------------------------------------------
#define GS_ROWW 20
#define GS_ARR  (128 * GS_ROWW)          // words per array (2560)
#define GS_STAGE (4 * GS_ARR)            // words per stage (10240)
#define GEMM_SMEM (3 * GS_STAGE * 4)     // bytes (122880)

__global__ void __launch_bounds__(256, 1) hgemm3_kernel(
    const __nv_bfloat16* __restrict__ Ah, const __nv_bfloat16* __restrict__ Al,
    const __nv_bfloat16* __restrict__ Bth, const __nv_bfloat16* __restrict__ Btl,
    float* __restrict__ C, int M, int N, int K)
{
    extern __shared__ uint32_t sg[];

    const int tid = threadIdx.x;
    const int wid = tid >> 5;
    const int lane = tid & 31;
    const int g = lane >> 2;
    const int tig = lane & 3;
    const int warp_m = wid >> 2;        // 0..1
    const int warp_n = wid & 3;         // 0..3
    const int row0 = blockIdx.y * 128;
    const int col0 = blockIdx.x * 128;

    const __nv_bfloat16* srcs[4] = {
        Ah + (size_t)row0 * K, Al + (size_t)row0 * K,
        Bth + (size_t)col0 * K, Btl + (size_t)col0 * K };

    const int ntiles = K >> 5;          // 64

    // issue cp.async for tile kt into stage st
    auto issue = [&](int kt, int st) {
        const uint32_t base = smem_u32(sg) + st * GS_STAGE * 4;
#pragma unroll
        for (int arr = 0; arr < 4; ++arr) {
            const uint32_t abase = base + arr * GS_ARR * 4;
#pragma unroll
            for (int c = 0; c < 2; ++c) {
                const int ch = tid + 256 * c;      // 0..511
                const int r = ch >> 2;
                const int seg = ch & 3;
                cp16(abase + (r * GS_ROWW + seg * 4) * 4,
                     srcs[arr] + (size_t)r * K + kt * 32 + seg * 8);
            }
        }
    };

    issue(0, 0); cp_commit();
    issue(1, 1); cp_commit();

    float acc[4][4][4];
#pragma unroll
    for (int mf = 0; mf < 4; ++mf)
#pragma unroll
        for (int nf = 0; nf < 4; ++nf)
#pragma unroll
            for (int r = 0; r < 4; ++r) acc[mf][nf][r] = 0.0f;

    for (int kt = 0; kt < ntiles; ++kt) {
        cp_wait<1>();
        __syncthreads();

        const int st = kt % 3;
        const uint32_t* Ash = sg + st * GS_STAGE;
        const uint32_t* Asl = Ash + GS_ARR;
        const uint32_t* Bsh = Asl + GS_ARR;
        const uint32_t* Bsl = Bsh + GS_ARR;

#pragma unroll
        for (int ks = 0; ks < 2; ++ks) {
            const int kw = 8 * ks + tig;
            uint32_t ah[4][4], al[4][4];
#pragma unroll
            for (int mf = 0; mf < 4; ++mf) {
                const int m = warp_m * 64 + mf * 16 + g;
                ah[mf][0] = Ash[m * GS_ROWW + kw];
                ah[mf][1] = Ash[(m + 8) * GS_ROWW + kw];
                ah[mf][2] = Ash[m * GS_ROWW + kw + 4];
                ah[mf][3] = Ash[(m + 8) * GS_ROWW + kw + 4];
                al[mf][0] = Asl[m * GS_ROWW + kw];
                al[mf][1] = Asl[(m + 8) * GS_ROWW + kw];
                al[mf][2] = Asl[m * GS_ROWW + kw + 4];
                al[mf][3] = Asl[(m + 8) * GS_ROWW + kw + 4];
            }
#pragma unroll
            for (int nf = 0; nf < 4; ++nf) {
                const int n = warp_n * 32 + nf * 8 + g;
                uint32_t bh[2], bl[2];
                bh[0] = Bsh[n * GS_ROWW + kw];
                bh[1] = Bsh[n * GS_ROWW + kw + 4];
                bl[0] = Bsl[n * GS_ROWW + kw];
                bl[1] = Bsl[n * GS_ROWW + kw + 4];
#pragma unroll
                for (int mf = 0; mf < 4; ++mf) {
                    mma_bf16(acc[mf][nf], ah[mf], bh);
                    mma_bf16(acc[mf][nf], ah[mf], bl);
                    mma_bf16(acc[mf][nf], al[mf], bh);
                }
            }
        }

        __syncthreads();
        if (kt + 2 < ntiles) issue(kt + 2, (kt + 2) % 3);
        cp_commit();
    }

    // Epilogue
#pragma unroll
    for (int mf = 0; mf < 4; ++mf) {
        const int row = row0 + warp_m * 64 + mf * 16 + g;
#pragma unroll
        for (int nf = 0; nf < 4; ++nf) {
            const int col = col0 + warp_n * 32 + nf * 8 + 2 * tig;
            *(float2*)&C[(size_t)row * N + col] =
                make_float2(acc[mf][nf][0], acc[mf][nf][1]);
            *(float2*)&C[(size_t)(row + 8) * N + col] =
                make_float2(acc[mf][nf][2], acc[mf][nf][3]);
        }
    }
}

// ---------------------------------------------------------------------------
// RoPE (unchanged)
// ---------------------------------------------------------------------------
__global__ void __launch_bounds__(256) rope_kernel(float* __restrict__ Q,
                                                   float* __restrict__ K)
{
    const int idx = blockIdx.x * blockDim.x + threadIdx.x;
    const int total = NTOK * NH * (HDIM / 2);
    if (idx >= total) return;

    const int j = idx & 63;
    const int h = (idx >> 6) & (NH - 1);
    const int t = idx >> 10;
    const int pos = t & (S_LEN - 1);

    const double inv = exp(-(double)j * (9.210340371976184 / 64.0));
    const float ang = (float)((double)pos * inv);
    float sn, cs;
    sincosf(ang, &sn, &cs);

    const size_t base = (size_t)t * DMODEL + (size_t)h * HDIM + j;
    const float q1 = Q[base], q2 = Q[base + 64];
    Q[base]      = q1 * cs - q2 * sn;
    Q[base + 64] = q2 * cs + q1 * sn;
    const float k1 = K[base], k2 = K[base + 64];
    K[base]      = k1 * cs - k2 * sn;
    K[base + 64] = k2 * cs + k1 * sn;
}

// ---------------------------------------------------------------------------
// Flash attention on tensor cores (bf16x3 exact, causal, tanh-cap 50, sink).
// CTA: 128 q-rows x (kv tiles of 64), 8 warps, warp = 16 q-rows.
// QK^T: warp m16 x n64 (8 nfrags, 8 ksteps over HD=128).
// PV:   warp m16 x n128 (16 nfrags, 4 ksteps over kv=64); P stays in regs.
// smem word strides: Q/K rows 68, V^T rows 36 (conflict-free frag loads).
// ---------------------------------------------------------------------------
#define FQH 0
#define FQL (FQH + 128 * 68)
#define FKH (FQL + 128 * 68)
#define FKL (FKH + 64 * 68)
#define FVH (FKL + 64 * 68)
#define FVL (FVH + 128 * 36)
#define FLASH_WORDS (FVL + 128 * 36)          // 35328 words
#define FLASH_SMEM (FLASH_WORDS * 4)          // 141312 bytes

__global__ void __launch_bounds__(256, 1) flash_mma_kernel(
    const float* __restrict__ Q, const float* __restrict__ K,
    const float* __restrict__ V, float* __restrict__ O)
{
    extern __shared__ uint32_t sf[];
    uint32_t* Qh = sf + FQH;
    uint32_t* Ql = sf + FQL;
    uint32_t* Kh = sf + FKH;
    uint32_t* Kl = sf + FKL;
    uint32_t* Vh = sf + FVH;   // transposed: [hd][kv]
    uint32_t* Vl = sf + FVL;

    const int qb = gridDim.x - 1 - blockIdx.x;   // long blocks first
    const int h = blockIdx.y;
    const int b = blockIdx.z;
    const int tid = threadIdx.x;
    const int wid = tid >> 5;
    const int lane = tid & 31;
    const int g = lane >> 2;
    const int tig = lane & 3;
    const int q0 = qb * 128;

    const float SCALE = 0.08838834764831845f;    // 1/sqrt(128)
    const float CAP = 50.0f;
    const float INV_CAP = 1.0f / 50.0f;

    const size_t hb = (size_t)b * S_LEN * DMODEL + (size_t)h * HDIM;
    const float* Qg = Q + hb;
    const float* Kg = K + hb;
    const float* Vg = V + hb;

    // ---- Q tile fill + split (once) ----
    for (int i = tid; i < 128 * 32; i += 256) {
        const int r = i >> 5;
        const int c4 = (i & 31) * 4;
        float4 q = *(const float4*)&Qg[(size_t)(q0 + r) * DMODEL + c4];
        uint32_t h0, l0, h1, l1;
        split2(q.x, q.y, h0, l0);
        split2(q.z, q.w, h1, l1);
        const int w = r * 68 + (c4 >> 1);
        Qh[w] = h0; Qh[w + 1] = h1;
        Ql[w] = l0; Ql[w + 1] = l1;
    }

    // O accumulators: 16 nfrags x 4
    float o[16][4];
#pragma unroll
    for (int nf = 0; nf < 16; ++nf)
#pragma unroll
        for (int r = 0; r < 4; ++r) o[nf][r] = 0.0f;

    float m0 = 0.0f, m1 = 0.0f;     // sink: logit 0
    float l0 = 1.0f, l1 = 1.0f;

    const int mrow0 = wid * 16 + g;     // local q-row of c0/c1
    const int kmax = 2 * qb + 1;

    for (int kb = 0; kb <= kmax; ++kb) {
        const int k0 = kb * 64;
        __syncthreads();   // previous PV done reading V

        // ---- K tile fill + split ----
        for (int i = tid; i < 64 * 32; i += 256) {
            const int r = i >> 5;
            const int c4 = (i & 31) * 4;
            float4 kv = *(const float4*)&Kg[(size_t)(k0 + r) * DMODEL + c4];
            uint32_t h0, lo0, h1, lo1;
            split2(kv.x, kv.y, h0, lo0);
            split2(kv.z, kv.w, h1, lo1);
            const int w = r * 68 + (c4 >> 1);
            Kh[w] = h0; Kh[w + 1] = h1;
            Kl[w] = lo0; Kl[w + 1] = lo1;
        }
        // ---- V tile fill, transposed + split ----
        for (int i = tid; i < 1024; i += 256) {
            const int r = i & 31;              // kv pair index
            const int c4 = ((i >> 5) & 31) * 4;
            float4 va = *(const float4*)&Vg[(size_t)(k0 + 2 * r) * DMODEL + c4];
            float4 vb = *(const float4*)&Vg[(size_t)(k0 + 2 * r + 1) * DMODEL + c4];
#pragma unroll
            for (int j = 0; j < 4; ++j) {
                const float a = (j == 0) ? va.x : (j == 1) ? va.y :
                                (j == 2) ? va.z : va.w;
                const float bb = (j == 0) ? vb.x : (j == 1) ? vb.y :
                                 (j == 2) ? vb.z : vb.w;
                uint32_t hh, ll;
                split2(a, bb, hh, ll);
                Vh[(c4 + j) * 36 + r] = hh;
                Vl[(c4 + j) * 36 + r] = ll;
            }
        }
        __syncthreads();

        // ---- S = Q K^T : 8 nfrags (n=64), 8 ksteps (k=128) ----
        float s[8][4];
#pragma unroll
        for (int nf = 0; nf < 8; ++nf)
#pragma unroll
            for (int r = 0; r < 4; ++r) s[nf][r] = 0.0f;

#pragma unroll
        for (int ks = 0; ks < 8; ++ks) {
            const int kw = 8 * ks + tig;
            uint32_t ah[4], al[4];
            const int ra = (wid * 16 + g) * 68;
            const int rb = (wid * 16 + g + 8) * 68;
            ah[0] = Qh[ra + kw];     ah[1] = Qh[rb + kw];
            ah[2] = Qh[ra + kw + 4]; ah[3] = Qh[rb + kw + 4];
            al[0] = Ql[ra + kw];     al[1] = Ql[rb + kw];
            al[2] = Ql[ra + kw + 4]; al[3] = Ql[rb + kw + 4];
#pragma unroll
            for (int nf = 0; nf < 8; ++nf) {
                const int n = (8 * nf + g) * 68;
                uint32_t bh[2], bl[2];
                bh[0] = Kh[n + kw];     bh[1] = Kh[n + kw + 4];
                bl[0] = Kl[n + kw];     bl[1] = Kl[n + kw + 4];
                mma_bf16(s[nf], ah, bh);
                mma_bf16(s[nf], ah, bl);
                mma_bf16(s[nf], al, bh);
            }
        }

        // ---- scale, tanh-cap, mask ----
        const bool need_mask = (kb >= 2 * qb);
        const int grow0 = q0 + mrow0;
        const int grow1 = grow0 + 8;
#pragma unroll
        for (int nf = 0; nf < 8; ++nf) {
#pragma unroll
            for (int r = 0; r < 4; ++r) {
                float v = s[nf][r] * SCALE;
                v = CAP * tanhf(v * INV_CAP);
                if (need_mask) {
                    const int col = k0 + 8 * nf + 2 * tig + (r & 1);
                    const int row = (r < 2) ? grow0 : grow1;
                    if (col > row) v = -INFINITY;
                }
                s[nf][r] = v;
            }
        }

        // ---- online softmax (rows g and g+8) ----
        float rmax0 = -3.4e38f, rmax1 = -3.4e38f;
#pragma unroll
        for (int nf = 0; nf < 8; ++nf) {
            rmax0 = fmaxf(rmax0, fmaxf(s[nf][0], s[nf][1]));
            rmax1 = fmaxf(rmax1, fmaxf(s[nf][2], s[nf][3]));
        }
#pragma unroll
        for (int w = 1; w < 4; w <<= 1) {
            rmax0 = fmaxf(rmax0, __shfl_xor_sync(0xffffffffu, rmax0, w));
            rmax1 = fmaxf(rmax1, __shfl_xor_sync(0xffffffffu, rmax1, w));
        }
        const float mn0 = fmaxf(m0, rmax0);
        const float mn1 = fmaxf(m1, rmax1);
        const float cr0 = __expf(m0 - mn0);
        const float cr1 = __expf(m1 - mn1);
        m0 = mn0; m1 = mn1;

        float rs0 = 0.0f, rs1 = 0.0f;
#pragma unroll
        for (int nf = 0; nf < 8; ++nf) {
            s[nf][0] = __expf(s[nf][0] - mn0);
            s[nf][1] = __expf(s[nf][1] - mn0);
            s[nf][2] = __expf(s[nf][2] - mn1);
            s[nf][3] = __expf(s[nf][3] - mn1);
            rs0 += s[nf][0] + s[nf][1];
            rs1 += s[nf][2] + s[nf][3];
        }
#pragma unroll
        for (int w = 1; w < 4; w <<= 1) {
            rs0 += __shfl_xor_sync(0xffffffffu, rs0, w);
            rs1 += __shfl_xor_sync(0xffffffffu, rs1, w);
        }
        l0 = l0 * cr0 + rs0;
        l1 = l1 * cr1 + rs1;

#pragma unroll
        for (int nf = 0; nf < 16; ++nf) {
            o[nf][0] *= cr0; o[nf][1] *= cr0;
            o[nf][2] *= cr1; o[nf][3] *= cr1;
        }

        // ---- O += P V : P register-resident (hi/lo), 4 ksteps x 16 nfrags ----
#pragma unroll
        for (int ks = 0; ks < 4; ++ks) {
            uint32_t ah[4], al[4];
            split2(s[2 * ks][0],     s[2 * ks][1],     ah[0], al[0]);
            split2(s[2 * ks][2],     s[2 * ks][3],     ah[1], al[1]);
            split2(s[2 * ks + 1][0], s[2 * ks + 1][1], ah[2], al[2]);
            split2(s[2 * ks + 1][2], s[2 * ks + 1][3], ah[3], al[3]);
            const int kw = 8 * ks + tig;
#pragma unroll
            for (int nf = 0; nf < 16; ++nf) {
                const int n = (8 * nf + g) * 36;
                uint32_t bh[2], bl[2];
                bh[0] = Vh[n + kw];     bh[1] = Vh[n + kw + 4];
                bl[0] = Vl[n + kw];     bl[1] = Vl[n + kw + 4];
                mma_bf16(o[nf], ah, bh);
                mma_bf16(o[nf], ah, bl);
                mma_bf16(o[nf], al, bh);
            }
        }
    }

    // ---- epilogue ----
    const float inv0 = 1.0f / l0;
    const float inv1 = 1.0f / l1;
    float* Og = O + hb;
    const int row0g = q0 + wid * 16 + g;
#pragma unroll
    for (int nf = 0; nf < 16; ++nf) {
        const int col = 8 * nf + 2 * tig;
        *(float2*)&Og[(size_t)row0g * DMODEL + col] =
            make_float2(o[nf][0] * inv0, o[nf][1] * inv0);
        *(float2*)&Og[(size_t)(row0g + 8) * DMODEL + col] =
            make_float2(o[nf][2] * inv1, o[nf][3] * inv1);
    }
}

// ---------------------------------------------------------------------------
extern "C" void kernel_launch(void* const* d_in, const int* in_sizes, int n_in,
                              void* d_out, int out_size)
{
    const float* x  = (const float*)d_in[0];
    const float* Wq = (const float*)d_in[1];
    const float* Wk = (const float*)d_in[2];
    const float* Wv = (const float*)d_in[3];
    const float* Wo = (const float*)d_in[4];
    float* out = (float*)d_out;

    float *Qp, *Kp, *Vp, *AOp;
    cudaGetSymbolAddress((void**)&Qp,  g_Q);
    cudaGetSymbolAddress((void**)&Kp,  g_K);
    cudaGetSymbolAddress((void**)&Vp,  g_V);
    cudaGetSymbolAddress((void**)&AOp, g_AO);

    __nv_bfloat16 *xh, *xl, *aoh, *aol;
    __nv_bfloat16 *wqh, *wql, *wkh, *wkl, *wvh, *wvl, *woh, *wol;
    cudaGetSymbolAddress((void**)&xh,  g_xh);
    cudaGetSymbolAddress((void**)&xl,  g_xl);
    cudaGetSymbolAddress((void**)&aoh, g_aoh);
    cudaGetSymbolAddress((void**)&aol, g_aol);
    cudaGetSymbolAddress((void**)&wqh, g_Wqh);
    cudaGetSymbolAddress((void**)&wql, g_Wql);
    cudaGetSymbolAddress((void**)&wkh, g_Wkh);
    cudaGetSymbolAddress((void**)&wkl, g_Wkl);
    cudaGetSymbolAddress((void**)&wvh, g_Wvh);
    cudaGetSymbolAddress((void**)&wvl, g_Wvl);
    cudaGetSymbolAddress((void**)&woh, g_Woh);
    cudaGetSymbolAddress((void**)&wol, g_Wol);

    cudaFuncSetAttribute(hgemm3_kernel,
                         cudaFuncAttributeMaxDynamicSharedMemorySize,
                         GEMM_SMEM);
    cudaFuncSetAttribute(flash_mma_kernel,
                         cudaFuncAttributeMaxDynamicSharedMemorySize,
                         FLASH_SMEM);

    // 1. pre-split inputs
    const int n2x = NTOK * DMODEL / 2;
    split_rows_kernel<<<n2x / 256, 256>>>(x, xh, xl, n2x);
    const dim3 gt(DMODEL / 32, DMODEL / 32);
    split_transpose_kernel<<<gt, 256>>>(Wq, wqh, wql, DMODEL, DMODEL);
    split_transpose_kernel<<<gt, 256>>>(Wk, wkh, wkl, DMODEL, DMODEL);
    split_transpose_kernel<<<gt, 256>>>(Wv, wvh, wvl, DMODEL, DMODEL);
    split_transpose_kernel<<<gt, 256>>>(Wo, woh, wol, DMODEL, DMODEL);

    // 2. QKV projections
    const dim3 gg(DMODEL / 128, NTOK / 128);   // (16, 32)
    hgemm3_kernel<<<gg, 256, GEMM_SMEM>>>(xh, xl, wqh, wql, Qp, NTOK, DMODEL, DMODEL);
    hgemm3_kernel<<<gg, 256, GEMM_SMEM>>>(xh, xl, wkh, wkl, Kp, NTOK, DMODEL, DMODEL);
    hgemm3_kernel<<<gg, 256, GEMM_SMEM>>>(xh, xl, wvh, wvl, Vp, NTOK, DMODEL, DMODEL);

    // 3. RoPE
    const int nrope = NTOK * NH * (HDIM / 2);
    rope_kernel<<<nrope / 256, 256>>>(Qp, Kp);

    // 4. flash attention
    const dim3 gf(S_LEN / 128, NH, BATCH);     // (16, 16, 2)
    flash_mma_kernel<<<gf, 256, FLASH_SMEM>>>(Qp, Kp, Vp, AOp);

    // 5. output projection
    split_rows_kernel<<<n2x / 256, 256>>>(AOp, aoh, aol, n2x);
    hgemm3_kernel<<<gg, 256, GEMM_SMEM>>>(aoh, aol, woh, wol, out, NTOK, DMODEL, DMODEL);
}

// round 5
// speedup vs baseline: 2.3263x; 1.0846x over previous
#include <cuda_runtime.h>
#include <cuda_bf16.h>
#include <math.h>
#include <stdint.h>

// Problem constants (B=2, S=2048, D=2048, H=16, HD=128)
#define S_LEN 2048
#define DMODEL 2048
#define NH 16
#define HDIM 128
#define BATCH 2
#define NTOK (BATCH * S_LEN)   // 4096

// ---------------------------------------------------------------------------
// Scratch (__device__ globals; allocation-free rule)
// ---------------------------------------------------------------------------
__device__ float g_Q[(size_t)NTOK * DMODEL];
__device__ float g_K[(size_t)NTOK * DMODEL];
__device__ float g_V[(size_t)NTOK * DMODEL];
__device__ float g_AO[(size_t)NTOK * DMODEL];

__device__ __nv_bfloat16 g_xh[(size_t)NTOK * DMODEL];
__device__ __nv_bfloat16 g_xl[(size_t)NTOK * DMODEL];
__device__ __nv_bfloat16 g_aoh[(size_t)NTOK * DMODEL];
__device__ __nv_bfloat16 g_aol[(size_t)NTOK * DMODEL];
__device__ __nv_bfloat16 g_Wqh[(size_t)DMODEL * DMODEL];
__device__ __nv_bfloat16 g_Wql[(size_t)DMODEL * DMODEL];
__device__ __nv_bfloat16 g_Wkh[(size_t)DMODEL * DMODEL];
__device__ __nv_bfloat16 g_Wkl[(size_t)DMODEL * DMODEL];
__device__ __nv_bfloat16 g_Wvh[(size_t)DMODEL * DMODEL];
__device__ __nv_bfloat16 g_Wvl[(size_t)DMODEL * DMODEL];
__device__ __nv_bfloat16 g_Woh[(size_t)DMODEL * DMODEL];
__device__ __nv_bfloat16 g_Wol[(size_t)DMODEL * DMODEL];

// ---------------------------------------------------------------------------
// Common helpers
// ---------------------------------------------------------------------------
__device__ __forceinline__ uint32_t pack_bf16x2(float lo, float hi) {
    uint32_t r;
    asm("cvt.rn.bf16x2.f32 %0, %1, %2;" : "=r"(r) : "f"(hi), "f"(lo));
    return r;
}
__device__ __forceinline__ void split2(float a, float b,
                                       uint32_t& h, uint32_t& l) {
    h = pack_bf16x2(a, b);
    float ha = __uint_as_float(h << 16);
    float hb = __uint_as_float(h & 0xffff0000u);
    l = pack_bf16x2(a - ha, b - hb);
}
__device__ __forceinline__ void mma_bf16(float* c, const uint32_t* a,
                                         const uint32_t* b) {
    asm volatile(
        "mma.sync.aligned.m16n8k16.row.col.f32.bf16.bf16.f32 "
        "{%0,%1,%2,%3}, {%4,%5,%6,%7}, {%8,%9}, {%0,%1,%2,%3};"
        : "+f"(c[0]), "+f"(c[1]), "+f"(c[2]), "+f"(c[3])
        : "r"(a[0]), "r"(a[1]), "r"(a[2]), "r"(a[3]), "r"(b[0]), "r"(b[1]));
}
__device__ __forceinline__ uint32_t smem_u32(const void* p) {
    return (uint32_t)__cvta_generic_to_shared(p);
}
__device__ __forceinline__ void cp16(uint32_t dst, const void* src) {
    asm volatile("cp.async.cg.shared.global [%0], [%1], 16;"
                 :: "r"(dst), "l"(src));
}
__device__ __forceinline__ void cp_commit() {
    asm volatile("cp.async.commit_group;");
}
template <int N>
__device__ __forceinline__ void cp_wait() {
    asm volatile("cp.async.wait_group %0;" :: "n"(N));
}
__device__ __forceinline__ void ldsm4(uint32_t& r0, uint32_t& r1,
                                      uint32_t& r2, uint32_t& r3,
                                      uint32_t addr) {
    asm volatile("ldmatrix.sync.aligned.m8n8.x4.shared.b16 {%0,%1,%2,%3}, [%4];"
                 : "=r"(r0), "=r"(r1), "=r"(r2), "=r"(r3) : "r"(addr));
}

// ---------------------------------------------------------------------------
// Pre-split kernels
// ---------------------------------------------------------------------------
__global__ void __launch_bounds__(256) split_rows_kernel(
    const float* __restrict__ X, __nv_bfloat16* __restrict__ H,
    __nv_bfloat16* __restrict__ L, int n2)
{
    int i = blockIdx.x * blockDim.x + threadIdx.x;
    if (i >= n2) return;
    float2 v = ((const float2*)X)[i];
    uint32_t h, l;
    split2(v.x, v.y, h, l);
    ((uint32_t*)H)[i] = h;
    ((uint32_t*)L)[i] = l;
}

__global__ void __launch_bounds__(256) split_transpose_kernel(
    const float* __restrict__ W, __nv_bfloat16* __restrict__ Th,
    __nv_bfloat16* __restrict__ Tl, int K, int N)
{
    __shared__ float t[32][33];
    const int k0 = blockIdx.x * 32;
    const int n0 = blockIdx.y * 32;
    const int tx = threadIdx.x & 31;
    const int ty = threadIdx.x >> 5;
#pragma unroll
    for (int i = 0; i < 4; ++i)
        t[ty + 8 * i][tx] = W[(size_t)(k0 + ty + 8 * i) * N + n0 + tx];
    __syncthreads();
#pragma unroll
    for (int i = 0; i < 4; ++i) {
        const int n = n0 + ty + 8 * i;
        const float v = t[tx][ty + 8 * i];
        __nv_bfloat16 h = __float2bfloat16_rn(v);
        __nv_bfloat16 l = __float2bfloat16_rn(v - __bfloat162float(h));
        Th[(size_t)n * K + k0 + tx] = h;
        Tl[(size_t)n * K + k0 + tx] = l;
    }
}

// ---------------------------------------------------------------------------
// bf16x3 GEMM v2 (ldmatrix + fused hi/lo rows + 2 CTA/SM).
// C[M,N] = (Ah+Al)[M,K] @ (Bth+Btl)^T, fp32 out.
// Block 128x128x32, 8 warps (2m x 4n), warp tile 64x32, 3 cp.async stages.
// smem row = 128B: [hi k0..31 | lo k0..31], swizzle: chunk16B ^= (row & 7).
// Stage = A 16KB + B 16KB = 32KB; 3 stages = 96KB -> 2 CTAs/SM.
// ---------------------------------------------------------------------------
#define G2_STAGE 32768
#define G2_SMEM (3 * G2_STAGE)

__global__ void __launch_bounds__(256, 2) hgemm3_kernel(
    const __nv_bfloat16* __restrict__ Ah, const __nv_bfloat16* __restrict__ Al,
    const __nv_bfloat16* __restrict__ Bth, const __nv_bfloat16* __restrict__ Btl,
    float* __restrict__ C, int M, int N, int K)
{
    extern __shared__ char smem[];
    const uint32_t sbase = smem_u32(smem);

    const int tid = threadIdx.x;
    const int wid = tid >> 5;
    const int lane = tid & 31;
    const int g = lane >> 2;
    const int tig = lane & 3;
    const int warp_m = wid >> 2;        // 0..1
    const int warp_n = wid & 3;         // 0..3
    const int row0 = blockIdx.y * 128;
    const int col0 = blockIdx.x * 128;

    const __nv_bfloat16* srcA[2] = { Ah + (size_t)row0 * K, Al + (size_t)row0 * K };
    const __nv_bfloat16* srcB[2] = { Bth + (size_t)col0 * K, Btl + (size_t)col0 * K };

    const int ntiles = K >> 5;          // K/32

    // fill k-tile kt into stage kt%3
    auto fill = [&](int kt) {
        const uint32_t sb = sbase + (kt % 3) * G2_STAGE;
        const int k0 = kt << 5;
        // 2048 chunks of 16B: A rows 0..127 (8 chunks each), then B
#pragma unroll
        for (int it = 0; it < 8; ++it) {
            const int idx = tid + it * 256;          // 0..2047
            const int isB = idx >> 10;               // 0: A, 1: B
            const int i = idx & 1023;
            const int r = i >> 3;                    // row 0..127
            const int ch = i & 7;                    // chunk 0..7 (0-3 hi, 4-7 lo)
            const __nv_bfloat16* s = (isB ? srcB : srcA)[ch >> 2];
            cp16(sb + isB * 16384 + r * 128 + ((ch ^ (r & 7)) << 4),
                 s + (size_t)r * K + k0 + (ch & 3) * 8);
        }
    };

    fill(0); cp_commit();
    fill(1); cp_commit();

    float acc[4][4][4];
#pragma unroll
    for (int mf = 0; mf < 4; ++mf)
#pragma unroll
        for (int nf = 0; nf < 4; ++nf)
#pragma unroll
            for (int r = 0; r < 4; ++r) acc[mf][nf][r] = 0.0f;

    // ldmatrix lane roles
    const int a_row = (lane & 7) + ((lane >> 3) & 1) * 8;   // row within 16
    const int a_chs = (lane >> 4) & 1;                      // chunk select
    const int b_row = (lane & 7) + ((lane >> 4) & 1) * 8;
    const int b_chs = (lane >> 3) & 1;

    for (int kt = 0; kt < ntiles; ++kt) {
        cp_wait<1>();
        __syncthreads();

        const uint32_t sA = sbase + (kt % 3) * G2_STAGE;
        const uint32_t sB = sA + 16384;

#pragma unroll
        for (int ks = 0; ks < 2; ++ks) {
            // ---- B fragments: 4 nf (hi + lo) ----
            uint32_t bh[4][2], bl[4][2];
#pragma unroll
            for (int nb = 0; nb < 2; ++nb) {
                const int r = warp_n * 32 + nb * 16 + b_row;
                const int ch = 2 * ks + b_chs;
                const uint32_t ah_ = sB + r * 128 + ((ch ^ (r & 7)) << 4);
                const uint32_t al_ = sB + r * 128 + (((ch + 4) ^ (r & 7)) << 4);
                ldsm4(bh[2*nb][0], bh[2*nb][1], bh[2*nb+1][0], bh[2*nb+1][1], ah_);
                ldsm4(bl[2*nb][0], bl[2*nb][1], bl[2*nb+1][0], bl[2*nb+1][1], al_);
            }
            // ---- A fragments per mf + mma ----
#pragma unroll
            for (int mf = 0; mf < 4; ++mf) {
                const int r = warp_m * 64 + mf * 16 + a_row;
                const int ch = 2 * ks + a_chs;
                uint32_t ahf[4], alf[4];
                ldsm4(ahf[0], ahf[1], ahf[2], ahf[3],
                      sA + r * 128 + ((ch ^ (r & 7)) << 4));
                ldsm4(alf[0], alf[1], alf[2], alf[3],
                      sA + r * 128 + (((ch + 4) ^ (r & 7)) << 4));
#pragma unroll
                for (int nf = 0; nf < 4; ++nf) {
                    mma_bf16(acc[mf][nf], ahf, bh[nf]);
                    mma_bf16(acc[mf][nf], ahf, bl[nf]);
                    mma_bf16(acc[mf][nf], alf, bh[nf]);
                }
            }
        }

        __syncthreads();
        if (kt + 2 < ntiles) fill(kt + 2);
        cp_commit();
    }

    // Epilogue
#pragma unroll
    for (int mf = 0; mf < 4; ++mf) {
        const int row = row0 + warp_m * 64 + mf * 16 + g;
#pragma unroll
        for (int nf = 0; nf < 4; ++nf) {
            const int col = col0 + warp_n * 32 + nf * 8 + 2 * tig;
            *(float2*)&C[(size_t)row * N + col] =
                make_float2(acc[mf][nf][0], acc[mf][nf][1]);
            *(float2*)&C[(size_t)(row + 8) * N + col] =
                make_float2(acc[mf][nf][2], acc[mf][nf][3]);
        }
    }
}

// ---------------------------------------------------------------------------
// RoPE (unchanged)
// ---------------------------------------------------------------------------
__global__ void __launch_bounds__(256) rope_kernel(float* __restrict__ Q,
                                                   float* __restrict__ K)
{
    const int idx = blockIdx.x * blockDim.x + threadIdx.x;
    const int total = NTOK * NH * (HDIM / 2);
    if (idx >= total) return;

    const int j = idx & 63;
    const int h = (idx >> 6) & (NH - 1);
    const int t = idx >> 10;
    const int pos = t & (S_LEN - 1);

    const double inv = exp(-(double)j * (9.210340371976184 / 64.0));
    const float ang = (float)((double)pos * inv);
    float sn, cs;
    sincosf(ang, &sn, &cs);

    const size_t base = (size_t)t * DMODEL + (size_t)h * HDIM + j;
    const float q1 = Q[base], q2 = Q[base + 64];
    Q[base]      = q1 * cs - q2 * sn;
    Q[base + 64] = q2 * cs + q1 * sn;
    const float k1 = K[base], k2 = K[base + 64];
    K[base]      = k1 * cs - k2 * sn;
    K[base + 64] = k2 * cs + k1 * sn;
}

// ---------------------------------------------------------------------------
// Flash attention on tensor cores (bf16x3, causal, tanh-cap 50, sink).
// (unchanged from round 3 — passing at rel_err 2.5e-5)
// ---------------------------------------------------------------------------
#define FQH 0
#define FQL (FQH + 128 * 68)
#define FKH (FQL + 128 * 68)
#define FKL (FKH + 64 * 68)
#define FVH (FKL + 64 * 68)
#define FVL (FVH + 128 * 36)
#define FLASH_WORDS (FVL + 128 * 36)
#define FLASH_SMEM (FLASH_WORDS * 4)

__global__ void __launch_bounds__(256, 1) flash_mma_kernel(
    const float* __restrict__ Q, const float* __restrict__ K,
    const float* __restrict__ V, float* __restrict__ O)
{
    extern __shared__ uint32_t sf[];
    uint32_t* Qh = sf + FQH;
    uint32_t* Ql = sf + FQL;
    uint32_t* Kh = sf + FKH;
    uint32_t* Kl = sf + FKL;
    uint32_t* Vh = sf + FVH;
    uint32_t* Vl = sf + FVL;

    const int qb = gridDim.x - 1 - blockIdx.x;
    const int h = blockIdx.y;
    const int b = blockIdx.z;
    const int tid = threadIdx.x;
    const int wid = tid >> 5;
    const int lane = tid & 31;
    const int g = lane >> 2;
    const int tig = lane & 3;
    const int q0 = qb * 128;

    const float SCALE = 0.08838834764831845f;
    const float CAP = 50.0f;
    const float INV_CAP = 1.0f / 50.0f;

    const size_t hb = (size_t)b * S_LEN * DMODEL + (size_t)h * HDIM;
    const float* Qg = Q + hb;
    const float* Kg = K + hb;
    const float* Vg = V + hb;

    for (int i = tid; i < 128 * 32; i += 256) {
        const int r = i >> 5;
        const int c4 = (i & 31) * 4;
        float4 q = *(const float4*)&Qg[(size_t)(q0 + r) * DMODEL + c4];
        uint32_t h0, l0, h1, l1;
        split2(q.x, q.y, h0, l0);
        split2(q.z, q.w, h1, l1);
        const int w = r * 68 + (c4 >> 1);
        Qh[w] = h0; Qh[w + 1] = h1;
        Ql[w] = l0; Ql[w + 1] = l1;
    }

    float o[16][4];
#pragma unroll
    for (int nf = 0; nf < 16; ++nf)
#pragma unroll
        for (int r = 0; r < 4; ++r) o[nf][r] = 0.0f;

    float m0 = 0.0f, m1 = 0.0f;
    float l0 = 1.0f, l1 = 1.0f;

    const int mrow0 = wid * 16 + g;
    const int kmax = 2 * qb + 1;

    for (int kb = 0; kb <= kmax; ++kb) {
        const int k0 = kb * 64;
        __syncthreads();

        for (int i = tid; i < 64 * 32; i += 256) {
            const int r = i >> 5;
            const int c4 = (i & 31) * 4;
            float4 kv = *(const float4*)&Kg[(size_t)(k0 + r) * DMODEL + c4];
            uint32_t h0, lo0, h1, lo1;
            split2(kv.x, kv.y, h0, lo0);
            split2(kv.z, kv.w, h1, lo1);
            const int w = r * 68 + (c4 >> 1);
            Kh[w] = h0; Kh[w + 1] = h1;
            Kl[w] = lo0; Kl[w + 1] = lo1;
        }
        for (int i = tid; i < 1024; i += 256) {
            const int r = i & 31;
            const int c4 = ((i >> 5) & 31) * 4;
            float4 va = *(const float4*)&Vg[(size_t)(k0 + 2 * r) * DMODEL + c4];
            float4 vb = *(const float4*)&Vg[(size_t)(k0 + 2 * r + 1) * DMODEL + c4];
#pragma unroll
            for (int j = 0; j < 4; ++j) {
                const float a = (j == 0) ? va.x : (j == 1) ? va.y :
                                (j == 2) ? va.z : va.w;
                const float bb = (j == 0) ? vb.x : (j == 1) ? vb.y :
                                 (j == 2) ? vb.z : vb.w;
                uint32_t hh, ll;
                split2(a, bb, hh, ll);
                Vh[(c4 + j) * 36 + r] = hh;
                Vl[(c4 + j) * 36 + r] = ll;
            }
        }
        __syncthreads();

        float s[8][4];
#pragma unroll
        for (int nf = 0; nf < 8; ++nf)
#pragma unroll
            for (int r = 0; r < 4; ++r) s[nf][r] = 0.0f;

#pragma unroll
        for (int ks = 0; ks < 8; ++ks) {
            const int kw = 8 * ks + tig;
            uint32_t ah[4], al[4];
            const int ra = (wid * 16 + g) * 68;
            const int rb = (wid * 16 + g + 8) * 68;
            ah[0] = Qh[ra + kw];     ah[1] = Qh[rb + kw];
            ah[2] = Qh[ra + kw + 4]; ah[3] = Qh[rb + kw + 4];
            al[0] = Ql[ra + kw];     al[1] = Ql[rb + kw];
            al[2] = Ql[ra + kw + 4]; al[3] = Ql[rb + kw + 4];
#pragma unroll
            for (int nf = 0; nf < 8; ++nf) {
                const int n = (8 * nf + g) * 68;
                uint32_t bh[2], bl[2];
                bh[0] = Kh[n + kw];     bh[1] = Kh[n + kw + 4];
                bl[0] = Kl[n + kw];     bl[1] = Kl[n + kw + 4];
                mma_bf16(s[nf], ah, bh);
                mma_bf16(s[nf], ah, bl);
                mma_bf16(s[nf], al, bh);
            }
        }

        const bool need_mask = (kb >= 2 * qb);
        const int grow0 = q0 + mrow0;
        const int grow1 = grow0 + 8;
#pragma unroll
        for (int nf = 0; nf < 8; ++nf) {
#pragma unroll
            for (int r = 0; r < 4; ++r) {
                float v = s[nf][r] * SCALE;
                v = CAP * tanhf(v * INV_CAP);
                if (need_mask) {
                    const int col = k0 + 8 * nf + 2 * tig + (r & 1);
                    const int row = (r < 2) ? grow0 : grow1;
                    if (col > row) v = -INFINITY;
                }
                s[nf][r] = v;
            }
        }

        float rmax0 = -3.4e38f, rmax1 = -3.4e38f;
#pragma unroll
        for (int nf = 0; nf < 8; ++nf) {
            rmax0 = fmaxf(rmax0, fmaxf(s[nf][0], s[nf][1]));
            rmax1 = fmaxf(rmax1, fmaxf(s[nf][2], s[nf][3]));
        }
#pragma unroll
        for (int w = 1; w < 4; w <<= 1) {
            rmax0 = fmaxf(rmax0, __shfl_xor_sync(0xffffffffu, rmax0, w));
            rmax1 = fmaxf(rmax1, __shfl_xor_sync(0xffffffffu, rmax1, w));
        }
        const float mn0 = fmaxf(m0, rmax0);
        const float mn1 = fmaxf(m1, rmax1);
        const float cr0 = __expf(m0 - mn0);
        const float cr1 = __expf(m1 - mn1);
        m0 = mn0; m1 = mn1;

        float rs0 = 0.0f, rs1 = 0.0f;
#pragma unroll
        for (int nf = 0; nf < 8; ++nf) {
            s[nf][0] = __expf(s[nf][0] - mn0);
            s[nf][1] = __expf(s[nf][1] - mn0);
            s[nf][2] = __expf(s[nf][2] - mn1);
            s[nf][3] = __expf(s[nf][3] - mn1);
            rs0 += s[nf][0] + s[nf][1];
            rs1 += s[nf][2] + s[nf][3];
        }
#pragma unroll
        for (int w = 1; w < 4; w <<= 1) {
            rs0 += __shfl_xor_sync(0xffffffffu, rs0, w);
            rs1 += __shfl_xor_sync(0xffffffffu, rs1, w);
        }
        l0 = l0 * cr0 + rs0;
        l1 = l1 * cr1 + rs1;

#pragma unroll
        for (int nf = 0; nf < 16; ++nf) {
            o[nf][0] *= cr0; o[nf][1] *= cr0;
            o[nf][2] *= cr1; o[nf][3] *= cr1;
        }

#pragma unroll
        for (int ks = 0; ks < 4; ++ks) {
            uint32_t ah[4], al[4];
            split2(s[2 * ks][0],     s[2 * ks][1],     ah[0], al[0]);
            split2(s[2 * ks][2],     s[2 * ks][3],     ah[1], al[1]);
            split2(s[2 * ks + 1][0], s[2 * ks + 1][1], ah[2], al[2]);
            split2(s[2 * ks + 1][2], s[2 * ks + 1][3], ah[3], al[3]);
            const int kw = 8 * ks + tig;
#pragma unroll
            for (int nf = 0; nf < 16; ++nf) {
                const int n = (8 * nf + g) * 36;
                uint32_t bh[2], bl[2];
                bh[0] = Vh[n + kw];     bh[1] = Vh[n + kw + 4];
                bl[0] = Vl[n + kw];     bl[1] = Vl[n + kw + 4];
                mma_bf16(o[nf], ah, bh);
                mma_bf16(o[nf], ah, bl);
                mma_bf16(o[nf], al, bh);
            }
        }
    }

    const float inv0 = 1.0f / l0;
    const float inv1 = 1.0f / l1;
    float* Og = O + hb;
    const int row0g = q0 + wid * 16 + g;
#pragma unroll
    for (int nf = 0; nf < 16; ++nf) {
        const int col = 8 * nf + 2 * tig;
        *(float2*)&Og[(size_t)row0g * DMODEL + col] =
            make_float2(o[nf][0] * inv0, o[nf][1] * inv0);
        *(float2*)&Og[(size_t)(row0g + 8) * DMODEL + col] =
            make_float2(o[nf][2] * inv1, o[nf][3] * inv1);
    }
}

// ---------------------------------------------------------------------------
extern "C" void kernel_launch(void* const* d_in, const int* in_sizes, int n_in,
                              void* d_out, int out_size)
{
    const float* x  = (const float*)d_in[0];
    const float* Wq = (const float*)d_in[1];
    const float* Wk = (const float*)d_in[2];
    const float* Wv = (const float*)d_in[3];
    const float* Wo = (const float*)d_in[4];
    float* out = (float*)d_out;

    float *Qp, *Kp, *Vp, *AOp;
    cudaGetSymbolAddress((void**)&Qp,  g_Q);
    cudaGetSymbolAddress((void**)&Kp,  g_K);
    cudaGetSymbolAddress((void**)&Vp,  g_V);
    cudaGetSymbolAddress((void**)&AOp, g_AO);

    __nv_bfloat16 *xh, *xl, *aoh, *aol;
    __nv_bfloat16 *wqh, *wql, *wkh, *wkl, *wvh, *wvl, *woh, *wol;
    cudaGetSymbolAddress((void**)&xh,  g_xh);
    cudaGetSymbolAddress((void**)&xl,  g_xl);
    cudaGetSymbolAddress((void**)&aoh, g_aoh);
    cudaGetSymbolAddress((void**)&aol, g_aol);
    cudaGetSymbolAddress((void**)&wqh, g_Wqh);
    cudaGetSymbolAddress((void**)&wql, g_Wql);
    cudaGetSymbolAddress((void**)&wkh, g_Wkh);
    cudaGetSymbolAddress((void**)&wkl, g_Wkl);
    cudaGetSymbolAddress((void**)&wvh, g_Wvh);
    cudaGetSymbolAddress((void**)&wvl, g_Wvl);
    cudaGetSymbolAddress((void**)&woh, g_Woh);
    cudaGetSymbolAddress((void**)&wol, g_Wol);

    cudaFuncSetAttribute(hgemm3_kernel,
                         cudaFuncAttributeMaxDynamicSharedMemorySize,
                         G2_SMEM);
    cudaFuncSetAttribute(flash_mma_kernel,
                         cudaFuncAttributeMaxDynamicSharedMemorySize,
                         FLASH_SMEM);

    // 1. pre-split inputs
    const int n2x = NTOK * DMODEL / 2;
    split_rows_kernel<<<n2x / 256, 256>>>(x, xh, xl, n2x);
    const dim3 gt(DMODEL / 32, DMODEL / 32);
    split_transpose_kernel<<<gt, 256>>>(Wq, wqh, wql, DMODEL, DMODEL);
    split_transpose_kernel<<<gt, 256>>>(Wk, wkh, wkl, DMODEL, DMODEL);
    split_transpose_kernel<<<gt, 256>>>(Wv, wvh, wvl, DMODEL, DMODEL);
    split_transpose_kernel<<<gt, 256>>>(Wo, woh, wol, DMODEL, DMODEL);

    // 2. QKV projections
    const dim3 gg(DMODEL / 128, NTOK / 128);   // (16, 32)
    hgemm3_kernel<<<gg, 256, G2_SMEM>>>(xh, xl, wqh, wql, Qp, NTOK, DMODEL, DMODEL);
    hgemm3_kernel<<<gg, 256, G2_SMEM>>>(xh, xl, wkh, wkl, Kp, NTOK, DMODEL, DMODEL);
    hgemm3_kernel<<<gg, 256, G2_SMEM>>>(xh, xl, wvh, wvl, Vp, NTOK, DMODEL, DMODEL);

    // 3. RoPE
    const int nrope = NTOK * NH * (HDIM / 2);
    rope_kernel<<<nrope / 256, 256>>>(Qp, Kp);

    // 4. flash attention
    const dim3 gf(S_LEN / 128, NH, BATCH);     // (16, 16, 2)
    flash_mma_kernel<<<gf, 256, FLASH_SMEM>>>(Qp, Kp, Vp, AOp);

    // 5. output projection
    split_rows_kernel<<<n2x / 256, 256>>>(AOp, aoh, aol, n2x);
    hgemm3_kernel<<<gg, 256, G2_SMEM>>>(aoh, aol, woh, wol, out, NTOK, DMODEL, DMODEL);
}

// round 6
// speedup vs baseline: 3.2491x; 1.3967x over previous
#include <cuda_runtime.h>
#include <cuda_bf16.h>
#include <cuda_fp16.h>
#include <math.h>
#include <stdint.h>

// Problem constants (B=2, S=2048, D=2048, H=16, HD=128)
#define S_LEN 2048
#define DMODEL 2048
#define NH 16
#define HDIM 128
#define BATCH 2
#define NTOK (BATCH * S_LEN)   // 4096

// ---------------------------------------------------------------------------
// Scratch (__device__ globals; allocation-free rule)
// ---------------------------------------------------------------------------
__device__ float g_Q[(size_t)NTOK * DMODEL];
__device__ float g_K[(size_t)NTOK * DMODEL];
__device__ float g_V[(size_t)NTOK * DMODEL];
__device__ float g_AO[(size_t)NTOK * DMODEL];

// fp16 split activations (hi/lo) and fp16 hi-only transposed weights [N][K]
__device__ __half g_xh[(size_t)NTOK * DMODEL];
__device__ __half g_xl[(size_t)NTOK * DMODEL];
__device__ __half g_aoh[(size_t)NTOK * DMODEL];
__device__ __half g_aol[(size_t)NTOK * DMODEL];
__device__ __half g_Wqh[(size_t)DMODEL * DMODEL];
__device__ __half g_Wkh[(size_t)DMODEL * DMODEL];
__device__ __half g_Wvh[(size_t)DMODEL * DMODEL];
__device__ __half g_Woh[(size_t)DMODEL * DMODEL];

// ---------------------------------------------------------------------------
// Helpers
// ---------------------------------------------------------------------------
__device__ __forceinline__ uint32_t pack_bf16x2(float lo, float hi) {
    uint32_t r;
    asm("cvt.rn.bf16x2.f32 %0, %1, %2;" : "=r"(r) : "f"(hi), "f"(lo));
    return r;
}
__device__ __forceinline__ void split2(float a, float b,
                                       uint32_t& h, uint32_t& l) {
    h = pack_bf16x2(a, b);
    float ha = __uint_as_float(h << 16);
    float hb = __uint_as_float(h & 0xffff0000u);
    l = pack_bf16x2(a - ha, b - hb);
}
__device__ __forceinline__ void mma_bf16(float* c, const uint32_t* a,
                                         const uint32_t* b) {
    asm volatile(
        "mma.sync.aligned.m16n8k16.row.col.f32.bf16.bf16.f32 "
        "{%0,%1,%2,%3}, {%4,%5,%6,%7}, {%8,%9}, {%0,%1,%2,%3};"
        : "+f"(c[0]), "+f"(c[1]), "+f"(c[2]), "+f"(c[3])
        : "r"(a[0]), "r"(a[1]), "r"(a[2]), "r"(a[3]), "r"(b[0]), "r"(b[1]));
}
__device__ __forceinline__ void mma_f16(float* c, const uint32_t* a,
                                        const uint32_t* b) {
    asm volatile(
        "mma.sync.aligned.m16n8k16.row.col.f32.f16.f16.f32 "
        "{%0,%1,%2,%3}, {%4,%5,%6,%7}, {%8,%9}, {%0,%1,%2,%3};"
        : "+f"(c[0]), "+f"(c[1]), "+f"(c[2]), "+f"(c[3])
        : "r"(a[0]), "r"(a[1]), "r"(a[2]), "r"(a[3]), "r"(b[0]), "r"(b[1]));
}
__device__ __forceinline__ uint32_t smem_u32(const void* p) {
    return (uint32_t)__cvta_generic_to_shared(p);
}
__device__ __forceinline__ void cp16(uint32_t dst, const void* src) {
    asm volatile("cp.async.cg.shared.global [%0], [%1], 16;"
                 :: "r"(dst), "l"(src));
}
__device__ __forceinline__ void cp_commit() {
    asm volatile("cp.async.commit_group;");
}
template <int N>
__device__ __forceinline__ void cp_wait() {
    asm volatile("cp.async.wait_group %0;" :: "n"(N));
}
__device__ __forceinline__ void ldsm4(uint32_t& r0, uint32_t& r1,
                                      uint32_t& r2, uint32_t& r3,
                                      uint32_t addr) {
    asm volatile("ldmatrix.sync.aligned.m8n8.x4.shared.b16 {%0,%1,%2,%3}, [%4];"
                 : "=r"(r0), "=r"(r1), "=r"(r2), "=r"(r3) : "r"(addr));
}

// ---------------------------------------------------------------------------
// Pre-split kernels (fp16 hi/lo for activations, fp16 hi for weights)
// ---------------------------------------------------------------------------
__global__ void __launch_bounds__(256) split_rows_h_kernel(
    const float* __restrict__ X, __half* __restrict__ H,
    __half* __restrict__ L, int n2)
{
    int i = blockIdx.x * blockDim.x + threadIdx.x;
    if (i >= n2) return;
    float2 v = ((const float2*)X)[i];
    __half2 h = __floats2half2_rn(v.x, v.y);
    float2 hb = __half22float2(h);
    __half2 l = __floats2half2_rn(v.x - hb.x, v.y - hb.y);
    ((__half2*)H)[i] = h;
    ((__half2*)L)[i] = l;
}

// W fp32 [K][N] -> transposed fp16 hi [N][K]
__global__ void __launch_bounds__(256) split_transpose_h_kernel(
    const float* __restrict__ W, __half* __restrict__ Th, int K, int N)
{
    __shared__ float t[32][33];
    const int k0 = blockIdx.x * 32;
    const int n0 = blockIdx.y * 32;
    const int tx = threadIdx.x & 31;
    const int ty = threadIdx.x >> 5;
#pragma unroll
    for (int i = 0; i < 4; ++i)
        t[ty + 8 * i][tx] = W[(size_t)(k0 + ty + 8 * i) * N + n0 + tx];
    __syncthreads();
#pragma unroll
    for (int i = 0; i < 4; ++i) {
        const int n = n0 + ty + 8 * i;
        Th[(size_t)n * K + k0 + tx] = __float2half_rn(t[tx][ty + 8 * i]);
    }
}

// ---------------------------------------------------------------------------
// fp16x2 GEMM: C[M,N] = (Ah+Al)[M,K] @ Bh^T, fp32 out. 2 MMAs per output frag.
// Block 128x128x64, 8 warps (2m x 4n), warp tile 64x32, 2 cp.async stages.
// Stage = Ah 16KB + Al 16KB + Bh 16KB = 48KB; 2 stages = 96KB -> 2 CTAs/SM.
// Rows are 128B (64 fp16 = one K-chunk); swizzle: chunk16 ^= (row & 7).
// Fused N-select: weight/output chosen by blockIdx.x>>4 (QKV fusion).
// ---------------------------------------------------------------------------
#define G3_STAGE 49152
#define G3_SMEM (2 * G3_STAGE)

__global__ void __launch_bounds__(256, 2) hgemm2_kernel(
    const __half* __restrict__ Ah, const __half* __restrict__ Al,
    const __half* __restrict__ B0, const __half* __restrict__ B1,
    const __half* __restrict__ B2,
    float* __restrict__ C0, float* __restrict__ C1, float* __restrict__ C2,
    int M, int N, int K)
{
    extern __shared__ char smem[];
    const uint32_t sbase = smem_u32(smem);

    const int tid = threadIdx.x;
    const int wid = tid >> 5;
    const int lane = tid & 31;
    const int g = lane >> 2;
    const int tig = lane & 3;
    const int warp_m = wid >> 2;
    const int warp_n = wid & 3;
    const int row0 = blockIdx.y * 128;
    const int sel = blockIdx.x >> 4;
    const int col0 = (blockIdx.x & 15) * 128;

    const __half* Bt = (sel == 0) ? B0 : (sel == 1) ? B1 : B2;
    float* C = (sel == 0) ? C0 : (sel == 1) ? C1 : C2;

    const __half* srcs[3] = {
        Ah + (size_t)row0 * K, Al + (size_t)row0 * K, Bt + (size_t)col0 * K };

    const int ntiles = K >> 6;   // K/64 = 32

    // fill k-tile kt into stage kt%2: 3 arrays x 128 rows x 8 chunks = 3072
    auto fill = [&](int kt) {
        const uint32_t sb = sbase + (kt & 1) * G3_STAGE;
        const int k0 = kt << 6;
#pragma unroll
        for (int it = 0; it < 12; ++it) {
            const int idx = tid + it * 256;          // 0..3071
            const int arr = idx >> 10;               // 0:Ah 1:Al 2:Bh
            const int i = idx & 1023;
            const int r = i >> 3;
            const int ch = i & 7;
            cp16(sb + arr * 16384 + r * 128 + ((ch ^ (r & 7)) << 4),
                 srcs[arr] + (size_t)r * K + k0 + ch * 8);
        }
    };

    fill(0); cp_commit();
    fill(1); cp_commit();

    float acc[4][4][4];
#pragma unroll
    for (int mf = 0; mf < 4; ++mf)
#pragma unroll
        for (int nf = 0; nf < 4; ++nf)
#pragma unroll
            for (int r = 0; r < 4; ++r) acc[mf][nf][r] = 0.0f;

    // ldmatrix lane roles
    const int a_row = (lane & 7) + ((lane >> 3) & 1) * 8;
    const int a_chs = (lane >> 4) & 1;
    const int b_row = (lane & 7) + ((lane >> 4) & 1) * 8;
    const int b_chs = (lane >> 3) & 1;

    for (int kt = 0; kt < ntiles; ++kt) {
        cp_wait<1>();
        __syncthreads();

        const uint32_t sA = sbase + (kt & 1) * G3_STAGE;
        const uint32_t sL = sA + 16384;
        const uint32_t sB = sA + 32768;

#pragma unroll
        for (int ks = 0; ks < 4; ++ks) {
            // B fragments (hi only): 4 nf
            uint32_t bh[4][2];
#pragma unroll
            for (int nb = 0; nb < 2; ++nb) {
                const int r = warp_n * 32 + nb * 16 + b_row;
                const int ch = 2 * ks + b_chs;
                ldsm4(bh[2*nb][0], bh[2*nb][1], bh[2*nb+1][0], bh[2*nb+1][1],
                      sB + r * 128 + ((ch ^ (r & 7)) << 4));
            }
#pragma unroll
            for (int mf = 0; mf < 4; ++mf) {
                const int r = warp_m * 64 + mf * 16 + a_row;
                const int ch = 2 * ks + a_chs;
                uint32_t ahf[4], alf[4];
                ldsm4(ahf[0], ahf[1], ahf[2], ahf[3],
                      sA + r * 128 + ((ch ^ (r & 7)) << 4));
                ldsm4(alf[0], alf[1], alf[2], alf[3],
                      sL + r * 128 + ((ch ^ (r & 7)) << 4));
#pragma unroll
                for (int nf = 0; nf < 4; ++nf) {
                    mma_f16(acc[mf][nf], ahf, bh[nf]);
                    mma_f16(acc[mf][nf], alf, bh[nf]);
                }
            }
        }

        __syncthreads();
        if (kt + 2 < ntiles) fill(kt + 2);
        cp_commit();
    }

    // Epilogue
#pragma unroll
    for (int mf = 0; mf < 4; ++mf) {
        const int row = row0 + warp_m * 64 + mf * 16 + g;
#pragma unroll
        for (int nf = 0; nf < 4; ++nf) {
            const int col = col0 + warp_n * 32 + nf * 8 + 2 * tig;
            *(float2*)&C[(size_t)row * N + col] =
                make_float2(acc[mf][nf][0], acc[mf][nf][1]);
            *(float2*)&C[(size_t)(row + 8) * N + col] =
                make_float2(acc[mf][nf][2], acc[mf][nf][3]);
        }
    }
}

// ---------------------------------------------------------------------------
// RoPE (unchanged)
// ---------------------------------------------------------------------------
__global__ void __launch_bounds__(256) rope_kernel(float* __restrict__ Q,
                                                   float* __restrict__ K)
{
    const int idx = blockIdx.x * blockDim.x + threadIdx.x;
    const int total = NTOK * NH * (HDIM / 2);
    if (idx >= total) return;

    const int j = idx & 63;
    const int h = (idx >> 6) & (NH - 1);
    const int t = idx >> 10;
    const int pos = t & (S_LEN - 1);

    const double inv = exp(-(double)j * (9.210340371976184 / 64.0));
    const float ang = (float)((double)pos * inv);
    float sn, cs;
    sincosf(ang, &sn, &cs);

    const size_t base = (size_t)t * DMODEL + (size_t)h * HDIM + j;
    const float q1 = Q[base], q2 = Q[base + 64];
    Q[base]      = q1 * cs - q2 * sn;
    Q[base + 64] = q2 * cs + q1 * sn;
    const float k1 = K[base], k2 = K[base + 64];
    K[base]      = k1 * cs - k2 * sn;
    K[base + 64] = k2 * cs + k1 * sn;
}

// ---------------------------------------------------------------------------
// Flash attention on tensor cores (bf16x3 exact, causal, tanh-cap 50, sink).
// (unchanged — passing at rel_err 2.5e-5)
// ---------------------------------------------------------------------------
#define FQH 0
#define FQL (FQH + 128 * 68)
#define FKH (FQL + 128 * 68)
#define FKL (FKH + 64 * 68)
#define FVH (FKL + 64 * 68)
#define FVL (FVH + 128 * 36)
#define FLASH_WORDS (FVL + 128 * 36)
#define FLASH_SMEM (FLASH_WORDS * 4)

__global__ void __launch_bounds__(256, 1) flash_mma_kernel(
    const float* __restrict__ Q, const float* __restrict__ K,
    const float* __restrict__ V, float* __restrict__ O)
{
    extern __shared__ uint32_t sf[];
    uint32_t* Qh = sf + FQH;
    uint32_t* Ql = sf + FQL;
    uint32_t* Kh = sf + FKH;
    uint32_t* Kl = sf + FKL;
    uint32_t* Vh = sf + FVH;
    uint32_t* Vl = sf + FVL;

    const int qb = gridDim.x - 1 - blockIdx.x;
    const int h = blockIdx.y;
    const int b = blockIdx.z;
    const int tid = threadIdx.x;
    const int wid = tid >> 5;
    const int lane = tid & 31;
    const int g = lane >> 2;
    const int tig = lane & 3;
    const int q0 = qb * 128;

    const float SCALE = 0.08838834764831845f;
    const float CAP = 50.0f;
    const float INV_CAP = 1.0f / 50.0f;

    const size_t hb = (size_t)b * S_LEN * DMODEL + (size_t)h * HDIM;
    const float* Qg = Q + hb;
    const float* Kg = K + hb;
    const float* Vg = V + hb;

    for (int i = tid; i < 128 * 32; i += 256) {
        const int r = i >> 5;
        const int c4 = (i & 31) * 4;
        float4 q = *(const float4*)&Qg[(size_t)(q0 + r) * DMODEL + c4];
        uint32_t h0, l0, h1, l1;
        split2(q.x, q.y, h0, l0);
        split2(q.z, q.w, h1, l1);
        const int w = r * 68 + (c4 >> 1);
        Qh[w] = h0; Qh[w + 1] = h1;
        Ql[w] = l0; Ql[w + 1] = l1;
    }

    float o[16][4];
#pragma unroll
    for (int nf = 0; nf < 16; ++nf)
#pragma unroll
        for (int r = 0; r < 4; ++r) o[nf][r] = 0.0f;

    float m0 = 0.0f, m1 = 0.0f;
    float l0 = 1.0f, l1 = 1.0f;

    const int mrow0 = wid * 16 + g;
    const int kmax = 2 * qb + 1;

    for (int kb = 0; kb <= kmax; ++kb) {
        const int k0 = kb * 64;
        __syncthreads();

        for (int i = tid; i < 64 * 32; i += 256) {
            const int r = i >> 5;
            const int c4 = (i & 31) * 4;
            float4 kv = *(const float4*)&Kg[(size_t)(k0 + r) * DMODEL + c4];
            uint32_t h0, lo0, h1, lo1;
            split2(kv.x, kv.y, h0, lo0);
            split2(kv.z, kv.w, h1, lo1);
            const int w = r * 68 + (c4 >> 1);
            Kh[w] = h0; Kh[w + 1] = h1;
            Kl[w] = lo0; Kl[w + 1] = lo1;
        }
        for (int i = tid; i < 1024; i += 256) {
            const int r = i & 31;
            const int c4 = ((i >> 5) & 31) * 4;
            float4 va = *(const float4*)&Vg[(size_t)(k0 + 2 * r) * DMODEL + c4];
            float4 vb = *(const float4*)&Vg[(size_t)(k0 + 2 * r + 1) * DMODEL + c4];
#pragma unroll
            for (int j = 0; j < 4; ++j) {
                const float a = (j == 0) ? va.x : (j == 1) ? va.y :
                                (j == 2) ? va.z : va.w;
                const float bb = (j == 0) ? vb.x : (j == 1) ? vb.y :
                                 (j == 2) ? vb.z : vb.w;
                uint32_t hh, ll;
                split2(a, bb, hh, ll);
                Vh[(c4 + j) * 36 + r] = hh;
                Vl[(c4 + j) * 36 + r] = ll;
            }
        }
        __syncthreads();

        float s[8][4];
#pragma unroll
        for (int nf = 0; nf < 8; ++nf)
#pragma unroll
            for (int r = 0; r < 4; ++r) s[nf][r] = 0.0f;

#pragma unroll
        for (int ks = 0; ks < 8; ++ks) {
            const int kw = 8 * ks + tig;
            uint32_t ah[4], al[4];
            const int ra = (wid * 16 + g) * 68;
            const int rb = (wid * 16 + g + 8) * 68;
            ah[0] = Qh[ra + kw];     ah[1] = Qh[rb + kw];
            ah[2] = Qh[ra + kw + 4]; ah[3] = Qh[rb + kw + 4];
            al[0] = Ql[ra + kw];     al[1] = Ql[rb + kw];
            al[2] = Ql[ra + kw + 4]; al[3] = Ql[rb + kw + 4];
#pragma unroll
            for (int nf = 0; nf < 8; ++nf) {
                const int n = (8 * nf + g) * 68;
                uint32_t bh[2], bl[2];
                bh[0] = Kh[n + kw];     bh[1] = Kh[n + kw + 4];
                bl[0] = Kl[n + kw];     bl[1] = Kl[n + kw + 4];
                mma_bf16(s[nf], ah, bh);
                mma_bf16(s[nf], ah, bl);
                mma_bf16(s[nf], al, bh);
            }
        }

        const bool need_mask = (kb >= 2 * qb);
        const int grow0 = q0 + mrow0;
        const int grow1 = grow0 + 8;
#pragma unroll
        for (int nf = 0; nf < 8; ++nf) {
#pragma unroll
            for (int r = 0; r < 4; ++r) {
                float v = s[nf][r] * SCALE;
                v = CAP * tanhf(v * INV_CAP);
                if (need_mask) {
                    const int col = k0 + 8 * nf + 2 * tig + (r & 1);
                    const int row = (r < 2) ? grow0 : grow1;
                    if (col > row) v = -INFINITY;
                }
                s[nf][r] = v;
            }
        }

        float rmax0 = -3.4e38f, rmax1 = -3.4e38f;
#pragma unroll
        for (int nf = 0; nf < 8; ++nf) {
            rmax0 = fmaxf(rmax0, fmaxf(s[nf][0], s[nf][1]));
            rmax1 = fmaxf(rmax1, fmaxf(s[nf][2], s[nf][3]));
        }
#pragma unroll
        for (int w = 1; w < 4; w <<= 1) {
            rmax0 = fmaxf(rmax0, __shfl_xor_sync(0xffffffffu, rmax0, w));
            rmax1 = fmaxf(rmax1, __shfl_xor_sync(0xffffffffu, rmax1, w));
        }
        const float mn0 = fmaxf(m0, rmax0);
        const float mn1 = fmaxf(m1, rmax1);
        const float cr0 = __expf(m0 - mn0);
        const float cr1 = __expf(m1 - mn1);
        m0 = mn0; m1 = mn1;

        float rs0 = 0.0f, rs1 = 0.0f;
#pragma unroll
        for (int nf = 0; nf < 8; ++nf) {
            s[nf][0] = __expf(s[nf][0] - mn0);
            s[nf][1] = __expf(s[nf][1] - mn0);
            s[nf][2] = __expf(s[nf][2] - mn1);
            s[nf][3] = __expf(s[nf][3] - mn1);
            rs0 += s[nf][0] + s[nf][1];
            rs1 += s[nf][2] + s[nf][3];
        }
#pragma unroll
        for (int w = 1; w < 4; w <<= 1) {
            rs0 += __shfl_xor_sync(0xffffffffu, rs0, w);
            rs1 += __shfl_xor_sync(0xffffffffu, rs1, w);
        }
        l0 = l0 * cr0 + rs0;
        l1 = l1 * cr1 + rs1;

#pragma unroll
        for (int nf = 0; nf < 16; ++nf) {
            o[nf][0] *= cr0; o[nf][1] *= cr0;
            o[nf][2] *= cr1; o[nf][3] *= cr1;
        }

#pragma unroll
        for (int ks = 0; ks < 4; ++ks) {
            uint32_t ah[4], al[4];
            split2(s[2 * ks][0],     s[2 * ks][1],     ah[0], al[0]);
            split2(s[2 * ks][2],     s[2 * ks][3],     ah[1], al[1]);
            split2(s[2 * ks + 1][0], s[2 * ks + 1][1], ah[2], al[2]);
            split2(s[2 * ks + 1][2], s[2 * ks + 1][3], ah[3], al[3]);
            const int kw = 8 * ks + tig;
#pragma unroll
            for (int nf = 0; nf < 16; ++nf) {
                const int n = (8 * nf + g) * 36;
                uint32_t bh[2], bl[2];
                bh[0] = Vh[n + kw];     bh[1] = Vh[n + kw + 4];
                bl[0] = Vl[n + kw];     bl[1] = Vl[n + kw + 4];
                mma_bf16(o[nf], ah, bh);
                mma_bf16(o[nf], ah, bl);
                mma_bf16(o[nf], al, bh);
            }
        }
    }

    const float inv0 = 1.0f / l0;
    const float inv1 = 1.0f / l1;
    float* Og = O + hb;
    const int row0g = q0 + wid * 16 + g;
#pragma unroll
    for (int nf = 0; nf < 16; ++nf) {
        const int col = 8 * nf + 2 * tig;
        *(float2*)&Og[(size_t)row0g * DMODEL + col] =
            make_float2(o[nf][0] * inv0, o[nf][1] * inv0);
        *(float2*)&Og[(size_t)(row0g + 8) * DMODEL + col] =
            make_float2(o[nf][2] * inv1, o[nf][3] * inv1);
    }
}

// ---------------------------------------------------------------------------
extern "C" void kernel_launch(void* const* d_in, const int* in_sizes, int n_in,
                              void* d_out, int out_size)
{
    const float* x  = (const float*)d_in[0];
    const float* Wq = (const float*)d_in[1];
    const float* Wk = (const float*)d_in[2];
    const float* Wv = (const float*)d_in[3];
    const float* Wo = (const float*)d_in[4];
    float* out = (float*)d_out;

    float *Qp, *Kp, *Vp, *AOp;
    cudaGetSymbolAddress((void**)&Qp,  g_Q);
    cudaGetSymbolAddress((void**)&Kp,  g_K);
    cudaGetSymbolAddress((void**)&Vp,  g_V);
    cudaGetSymbolAddress((void**)&AOp, g_AO);

    __half *xh, *xl, *aoh, *aol, *wqh, *wkh, *wvh, *woh;
    cudaGetSymbolAddress((void**)&xh,  g_xh);
    cudaGetSymbolAddress((void**)&xl,  g_xl);
    cudaGetSymbolAddress((void**)&aoh, g_aoh);
    cudaGetSymbolAddress((void**)&aol, g_aol);
    cudaGetSymbolAddress((void**)&wqh, g_Wqh);
    cudaGetSymbolAddress((void**)&wkh, g_Wkh);
    cudaGetSymbolAddress((void**)&wvh, g_Wvh);
    cudaGetSymbolAddress((void**)&woh, g_Woh);

    cudaFuncSetAttribute(hgemm2_kernel,
                         cudaFuncAttributeMaxDynamicSharedMemorySize,
                         G3_SMEM);
    cudaFuncSetAttribute(flash_mma_kernel,
                         cudaFuncAttributeMaxDynamicSharedMemorySize,
                         FLASH_SMEM);

    // 1. pre-split inputs
    const int n2x = NTOK * DMODEL / 2;
    split_rows_h_kernel<<<n2x / 256, 256>>>(x, xh, xl, n2x);
    const dim3 gt(DMODEL / 32, DMODEL / 32);
    split_transpose_h_kernel<<<gt, 256>>>(Wq, wqh, DMODEL, DMODEL);
    split_transpose_h_kernel<<<gt, 256>>>(Wk, wkh, DMODEL, DMODEL);
    split_transpose_h_kernel<<<gt, 256>>>(Wv, wvh, DMODEL, DMODEL);
    split_transpose_h_kernel<<<gt, 256>>>(Wo, woh, DMODEL, DMODEL);

    // 2. fused QKV projection (one launch; weight selected per CTA)
    const dim3 gqkv(3 * DMODEL / 128, NTOK / 128);   // (48, 32)
    hgemm2_kernel<<<gqkv, 256, G3_SMEM>>>(xh, xl, wqh, wkh, wvh,
                                          Qp, Kp, Vp, NTOK, DMODEL, DMODEL);

    // 3. RoPE
    const int nrope = NTOK * NH * (HDIM / 2);
    rope_kernel<<<nrope / 256, 256>>>(Qp, Kp);

    // 4. flash attention (bf16x3, exact)
    const dim3 gf(S_LEN / 128, NH, BATCH);           // (16, 16, 2)
    flash_mma_kernel<<<gf, 256, FLASH_SMEM>>>(Qp, Kp, Vp, AOp);

    // 5. output projection
    split_rows_h_kernel<<<n2x / 256, 256>>>(AOp, aoh, aol, n2x);
    const dim3 go(DMODEL / 128, NTOK / 128);         // (16, 32)
    hgemm2_kernel<<<go, 256, G3_SMEM>>>(aoh, aol, woh, woh, woh,
                                        out, out, out, NTOK, DMODEL, DMODEL);
}

// round 7
// speedup vs baseline: 5.1237x; 1.5769x over previous
#include <cuda_runtime.h>
#include <cuda_fp16.h>
#include <math.h>
#include <stdint.h>

// Problem constants (B=2, S=2048, D=2048, H=16, HD=128)
#define S_LEN 2048
#define DMODEL 2048
#define NH 16
#define HDIM 128
#define BATCH 2
#define NTOK (BATCH * S_LEN)   // 4096

// ---------------------------------------------------------------------------
// Scratch (__device__ globals; allocation-free rule)
// ---------------------------------------------------------------------------
__device__ float g_Q[(size_t)NTOK * DMODEL];
__device__ float g_K[(size_t)NTOK * DMODEL];
__device__ float g_V[(size_t)NTOK * DMODEL];
__device__ float g_AO[(size_t)NTOK * DMODEL];

__device__ __half g_xh[(size_t)NTOK * DMODEL];
__device__ __half g_aoh[(size_t)NTOK * DMODEL];
__device__ __half g_Wqh[(size_t)DMODEL * DMODEL];
__device__ __half g_Wkh[(size_t)DMODEL * DMODEL];
__device__ __half g_Wvh[(size_t)DMODEL * DMODEL];
__device__ __half g_Woh[(size_t)DMODEL * DMODEL];

// ---------------------------------------------------------------------------
// Helpers
// ---------------------------------------------------------------------------
__device__ __forceinline__ uint32_t packh2(float a, float b) {
    __half2 h = __floats2half2_rn(a, b);
    return *(uint32_t*)&h;
}
// exact fp16 hi/lo split of two fp32 values
__device__ __forceinline__ void split2h(float a, float b,
                                        uint32_t& h, uint32_t& l) {
    __half2 hh = __floats2half2_rn(a, b);
    float2 hf = __half22float2(hh);
    __half2 ll = __floats2half2_rn(a - hf.x, b - hf.y);
    h = *(uint32_t*)&hh;
    l = *(uint32_t*)&ll;
}
__device__ __forceinline__ void mma_f16(float* c, const uint32_t* a,
                                        const uint32_t* b) {
    asm volatile(
        "mma.sync.aligned.m16n8k16.row.col.f32.f16.f16.f32 "
        "{%0,%1,%2,%3}, {%4,%5,%6,%7}, {%8,%9}, {%0,%1,%2,%3};"
        : "+f"(c[0]), "+f"(c[1]), "+f"(c[2]), "+f"(c[3])
        : "r"(a[0]), "r"(a[1]), "r"(a[2]), "r"(a[3]), "r"(b[0]), "r"(b[1]));
}
__device__ __forceinline__ uint32_t smem_u32(const void* p) {
    return (uint32_t)__cvta_generic_to_shared(p);
}
__device__ __forceinline__ void cp16(uint32_t dst, const void* src) {
    asm volatile("cp.async.cg.shared.global [%0], [%1], 16;"
                 :: "r"(dst), "l"(src));
}
__device__ __forceinline__ void cp_commit() {
    asm volatile("cp.async.commit_group;");
}
template <int N>
__device__ __forceinline__ void cp_wait() {
    asm volatile("cp.async.wait_group %0;" :: "n"(N));
}
__device__ __forceinline__ void ldsm4(uint32_t& r0, uint32_t& r1,
                                      uint32_t& r2, uint32_t& r3,
                                      uint32_t addr) {
    asm volatile("ldmatrix.sync.aligned.m8n8.x4.shared.b16 {%0,%1,%2,%3}, [%4];"
                 : "=r"(r0), "=r"(r1), "=r"(r2), "=r"(r3) : "r"(addr));
}

// ---------------------------------------------------------------------------
// Conversion kernels
// ---------------------------------------------------------------------------
__global__ void __launch_bounds__(256) conv_h_kernel(
    const float* __restrict__ X, __half* __restrict__ H, int n2)
{
    int i = blockIdx.x * blockDim.x + threadIdx.x;
    if (i >= n2) return;
    float2 v = ((const float2*)X)[i];
    ((uint32_t*)H)[i] = packh2(v.x, v.y);
}

// W fp32 [K][N] -> transposed fp16 [N][K]
__global__ void __launch_bounds__(256) transpose_h_kernel(
    const float* __restrict__ W, __half* __restrict__ Th, int K, int N)
{
    __shared__ float t[32][33];
    const int k0 = blockIdx.x * 32;
    const int n0 = blockIdx.y * 32;
    const int tx = threadIdx.x & 31;
    const int ty = threadIdx.x >> 5;
#pragma unroll
    for (int i = 0; i < 4; ++i)
        t[ty + 8 * i][tx] = W[(size_t)(k0 + ty + 8 * i) * N + n0 + tx];
    __syncthreads();
#pragma unroll
    for (int i = 0; i < 4; ++i) {
        const int n = n0 + ty + 8 * i;
        Th[(size_t)n * K + k0 + tx] = __float2half_rn(t[tx][ty + 8 * i]);
    }
}

// ---------------------------------------------------------------------------
// fp16 single-term GEMM: C[M,N] = Ah[M,K] @ Bh^T, fp32 out. 1 MMA per frag.
// Block 128x128x64, 8 warps (2m x 4n), warp tile 64x32, 3 cp.async stages.
// Stage = A 16KB + B 16KB = 32KB; 3 stages = 96KB -> 2 CTAs/SM.
// Rows 128B (64 fp16 = one K-chunk); swizzle: chunk16 ^= (row & 7).
// Fused N-select: weight/output chosen by blockIdx.x>>4 (QKV fusion).
// ---------------------------------------------------------------------------
#define G_STAGE 32768
#define G_SMEM (3 * G_STAGE)

__global__ void __launch_bounds__(256, 2) hgemm1_kernel(
    const __half* __restrict__ Ah,
    const __half* __restrict__ B0, const __half* __restrict__ B1,
    const __half* __restrict__ B2,
    float* __restrict__ C0, float* __restrict__ C1, float* __restrict__ C2,
    int M, int N, int K)
{
    extern __shared__ char smem[];
    const uint32_t sbase = smem_u32(smem);

    const int tid = threadIdx.x;
    const int wid = tid >> 5;
    const int lane = tid & 31;
    const int g = lane >> 2;
    const int tig = lane & 3;
    const int warp_m = wid >> 2;
    const int warp_n = wid & 3;
    const int row0 = blockIdx.y * 128;
    const int sel = blockIdx.x >> 4;
    const int col0 = (blockIdx.x & 15) * 128;

    const __half* Bt = (sel == 0) ? B0 : (sel == 1) ? B1 : B2;
    float* C = (sel == 0) ? C0 : (sel == 1) ? C1 : C2;

    const __half* srcs[2] = { Ah + (size_t)row0 * K, Bt + (size_t)col0 * K };

    const int ntiles = K >> 6;   // 32

    auto fill = [&](int kt) {
        const uint32_t sb = sbase + (kt % 3) * G_STAGE;
        const int k0 = kt << 6;
#pragma unroll
        for (int it = 0; it < 8; ++it) {
            const int idx = tid + it * 256;          // 0..2047
            const int arr = idx >> 10;               // 0:A 1:B
            const int i = idx & 1023;
            const int r = i >> 3;
            const int ch = i & 7;
            cp16(sb + arr * 16384 + r * 128 + ((ch ^ (r & 7)) << 4),
                 srcs[arr] + (size_t)r * K + k0 + ch * 8);
        }
    };

    fill(0); cp_commit();
    fill(1); cp_commit();

    float acc[4][4][4];
#pragma unroll
    for (int mf = 0; mf < 4; ++mf)
#pragma unroll
        for (int nf = 0; nf < 4; ++nf)
#pragma unroll
            for (int r = 0; r < 4; ++r) acc[mf][nf][r] = 0.0f;

    const int a_row = (lane & 7) + ((lane >> 3) & 1) * 8;
    const int a_chs = (lane >> 4) & 1;
    const int b_row = (lane & 7) + ((lane >> 4) & 1) * 8;
    const int b_chs = (lane >> 3) & 1;

    for (int kt = 0; kt < ntiles; ++kt) {
        cp_wait<1>();
        __syncthreads();

        const uint32_t sA = sbase + (kt % 3) * G_STAGE;
        const uint32_t sB = sA + 16384;

#pragma unroll
        for (int ks = 0; ks < 4; ++ks) {
            uint32_t bh[4][2];
#pragma unroll
            for (int nb = 0; nb < 2; ++nb) {
                const int r = warp_n * 32 + nb * 16 + b_row;
                const int ch = 2 * ks + b_chs;
                ldsm4(bh[2*nb][0], bh[2*nb][1], bh[2*nb+1][0], bh[2*nb+1][1],
                      sB + r * 128 + ((ch ^ (r & 7)) << 4));
            }
#pragma unroll
            for (int mf = 0; mf < 4; ++mf) {
                const int r = warp_m * 64 + mf * 16 + a_row;
                const int ch = 2 * ks + a_chs;
                uint32_t af[4];
                ldsm4(af[0], af[1], af[2], af[3],
                      sA + r * 128 + ((ch ^ (r & 7)) << 4));
#pragma unroll
                for (int nf = 0; nf < 4; ++nf)
                    mma_f16(acc[mf][nf], af, bh[nf]);
            }
        }

        __syncthreads();
        if (kt + 2 < ntiles) fill(kt + 2);
        cp_commit();
    }

#pragma unroll
    for (int mf = 0; mf < 4; ++mf) {
        const int row = row0 + warp_m * 64 + mf * 16 + g;
#pragma unroll
        for (int nf = 0; nf < 4; ++nf) {
            const int col = col0 + warp_n * 32 + nf * 8 + 2 * tig;
            *(float2*)&C[(size_t)row * N + col] =
                make_float2(acc[mf][nf][0], acc[mf][nf][1]);
            *(float2*)&C[(size_t)(row + 8) * N + col] =
                make_float2(acc[mf][nf][2], acc[mf][nf][3]);
        }
    }
}

// ---------------------------------------------------------------------------
// RoPE (unchanged)
// ---------------------------------------------------------------------------
__global__ void __launch_bounds__(256) rope_kernel(float* __restrict__ Q,
                                                   float* __restrict__ K)
{
    const int idx = blockIdx.x * blockDim.x + threadIdx.x;
    const int total = NTOK * NH * (HDIM / 2);
    if (idx >= total) return;

    const int j = idx & 63;
    const int h = (idx >> 6) & (NH - 1);
    const int t = idx >> 10;
    const int pos = t & (S_LEN - 1);

    const double inv = exp(-(double)j * (9.210340371976184 / 64.0));
    const float ang = (float)((double)pos * inv);
    float sn, cs;
    sincosf(ang, &sn, &cs);

    const size_t base = (size_t)t * DMODEL + (size_t)h * HDIM + j;
    const float q1 = Q[base], q2 = Q[base + 64];
    Q[base]      = q1 * cs - q2 * sn;
    Q[base + 64] = q2 * cs + q1 * sn;
    const float k1 = K[base], k2 = K[base + 64];
    K[base]      = k1 * cs - k2 * sn;
    K[base + 64] = k2 * cs + k1 * sn;
}

// ---------------------------------------------------------------------------
// Flash attention, fp16 reduced-term (causal, tanh-cap 50, sink logit 0).
// Q exact (fp16 hi+lo), K rounded fp16 -> QK^T = 2 MMAs per frag.
// P exact (fp16 hi+lo), V rounded fp16 -> PV  = 2 MMAs per frag.
// CTA: 128 q-rows x kv-tiles of 64; 8 warps; warp = 16 q-rows.
// smem ~103KB -> 2 CTAs/SM.
// ---------------------------------------------------------------------------
#define FQH 0
#define FQL (FQH + 128 * 68)
#define FKH (FQL + 128 * 68)
#define FVH (FKH + 64 * 68)
#define FLASH_WORDS (FVH + 128 * 36)      // 26368 words
#define FLASH_SMEM (FLASH_WORDS * 4)      // 105472 bytes

__global__ void __launch_bounds__(256, 2) flash_mma_kernel(
    const float* __restrict__ Q, const float* __restrict__ K,
    const float* __restrict__ V, float* __restrict__ O)
{
    extern __shared__ uint32_t sf[];
    uint32_t* Qh = sf + FQH;
    uint32_t* Ql = sf + FQL;
    uint32_t* Kh = sf + FKH;
    uint32_t* Vh = sf + FVH;   // transposed: [hd][kv]

    const int qb = gridDim.x - 1 - blockIdx.x;
    const int h = blockIdx.y;
    const int b = blockIdx.z;
    const int tid = threadIdx.x;
    const int wid = tid >> 5;
    const int lane = tid & 31;
    const int g = lane >> 2;
    const int tig = lane & 3;
    const int q0 = qb * 128;

    const float SCALE = 0.08838834764831845f;
    const float CAP = 50.0f;
    const float INV_CAP = 1.0f / 50.0f;

    const size_t hb = (size_t)b * S_LEN * DMODEL + (size_t)h * HDIM;
    const float* Qg = Q + hb;
    const float* Kg = K + hb;
    const float* Vg = V + hb;

    // Q tile fill + exact fp16 split
    for (int i = tid; i < 128 * 32; i += 256) {
        const int r = i >> 5;
        const int c4 = (i & 31) * 4;
        float4 q = *(const float4*)&Qg[(size_t)(q0 + r) * DMODEL + c4];
        uint32_t h0, l0, h1, l1;
        split2h(q.x, q.y, h0, l0);
        split2h(q.z, q.w, h1, l1);
        const int w = r * 68 + (c4 >> 1);
        Qh[w] = h0; Qh[w + 1] = h1;
        Ql[w] = l0; Ql[w + 1] = l1;
    }

    float o[16][4];
#pragma unroll
    for (int nf = 0; nf < 16; ++nf)
#pragma unroll
        for (int r = 0; r < 4; ++r) o[nf][r] = 0.0f;

    float m0 = 0.0f, m1 = 0.0f;   // sink logit 0
    float l0 = 1.0f, l1 = 1.0f;

    const int mrow0 = wid * 16 + g;
    const int kmax = 2 * qb + 1;

    for (int kb = 0; kb <= kmax; ++kb) {
        const int k0 = kb * 64;
        __syncthreads();

        // K tile: single fp16
        for (int i = tid; i < 64 * 32; i += 256) {
            const int r = i >> 5;
            const int c4 = (i & 31) * 4;
            float4 kv = *(const float4*)&Kg[(size_t)(k0 + r) * DMODEL + c4];
            const int w = r * 68 + (c4 >> 1);
            Kh[w]     = packh2(kv.x, kv.y);
            Kh[w + 1] = packh2(kv.z, kv.w);
        }
        // V tile: single fp16, transposed
        for (int i = tid; i < 1024; i += 256) {
            const int r = i & 31;
            const int c4 = ((i >> 5) & 31) * 4;
            float4 va = *(const float4*)&Vg[(size_t)(k0 + 2 * r) * DMODEL + c4];
            float4 vb = *(const float4*)&Vg[(size_t)(k0 + 2 * r + 1) * DMODEL + c4];
            Vh[(c4 + 0) * 36 + r] = packh2(va.x, vb.x);
            Vh[(c4 + 1) * 36 + r] = packh2(va.y, vb.y);
            Vh[(c4 + 2) * 36 + r] = packh2(va.z, vb.z);
            Vh[(c4 + 3) * 36 + r] = packh2(va.w, vb.w);
        }
        __syncthreads();

        // S = Q K^T : 8 nfrags, 8 ksteps, 2 MMAs each
        float s[8][4];
#pragma unroll
        for (int nf = 0; nf < 8; ++nf)
#pragma unroll
            for (int r = 0; r < 4; ++r) s[nf][r] = 0.0f;

#pragma unroll
        for (int ks = 0; ks < 8; ++ks) {
            const int kw = 8 * ks + tig;
            uint32_t ah[4], al[4];
            const int ra = (wid * 16 + g) * 68;
            const int rb = (wid * 16 + g + 8) * 68;
            ah[0] = Qh[ra + kw];     ah[1] = Qh[rb + kw];
            ah[2] = Qh[ra + kw + 4]; ah[3] = Qh[rb + kw + 4];
            al[0] = Ql[ra + kw];     al[1] = Ql[rb + kw];
            al[2] = Ql[ra + kw + 4]; al[3] = Ql[rb + kw + 4];
#pragma unroll
            for (int nf = 0; nf < 8; ++nf) {
                const int n = (8 * nf + g) * 68;
                uint32_t bh[2];
                bh[0] = Kh[n + kw]; bh[1] = Kh[n + kw + 4];
                mma_f16(s[nf], ah, bh);
                mma_f16(s[nf], al, bh);
            }
        }

        // scale, tanh-cap, causal mask
        const bool need_mask = (kb >= 2 * qb);
        const int grow0 = q0 + mrow0;
        const int grow1 = grow0 + 8;
#pragma unroll
        for (int nf = 0; nf < 8; ++nf) {
#pragma unroll
            for (int r = 0; r < 4; ++r) {
                float v = s[nf][r] * SCALE;
                v = CAP * tanhf(v * INV_CAP);
                if (need_mask) {
                    const int col = k0 + 8 * nf + 2 * tig + (r & 1);
                    const int row = (r < 2) ? grow0 : grow1;
                    if (col > row) v = -INFINITY;
                }
                s[nf][r] = v;
            }
        }

        // online softmax
        float rmax0 = -3.4e38f, rmax1 = -3.4e38f;
#pragma unroll
        for (int nf = 0; nf < 8; ++nf) {
            rmax0 = fmaxf(rmax0, fmaxf(s[nf][0], s[nf][1]));
            rmax1 = fmaxf(rmax1, fmaxf(s[nf][2], s[nf][3]));
        }
#pragma unroll
        for (int w = 1; w < 4; w <<= 1) {
            rmax0 = fmaxf(rmax0, __shfl_xor_sync(0xffffffffu, rmax0, w));
            rmax1 = fmaxf(rmax1, __shfl_xor_sync(0xffffffffu, rmax1, w));
        }
        const float mn0 = fmaxf(m0, rmax0);
        const float mn1 = fmaxf(m1, rmax1);
        const float cr0 = __expf(m0 - mn0);
        const float cr1 = __expf(m1 - mn1);
        m0 = mn0; m1 = mn1;

        float rs0 = 0.0f, rs1 = 0.0f;
#pragma unroll
        for (int nf = 0; nf < 8; ++nf) {
            s[nf][0] = __expf(s[nf][0] - mn0);
            s[nf][1] = __expf(s[nf][1] - mn0);
            s[nf][2] = __expf(s[nf][2] - mn1);
            s[nf][3] = __expf(s[nf][3] - mn1);
            rs0 += s[nf][0] + s[nf][1];
            rs1 += s[nf][2] + s[nf][3];
        }
#pragma unroll
        for (int w = 1; w < 4; w <<= 1) {
            rs0 += __shfl_xor_sync(0xffffffffu, rs0, w);
            rs1 += __shfl_xor_sync(0xffffffffu, rs1, w);
        }
        l0 = l0 * cr0 + rs0;
        l1 = l1 * cr1 + rs1;

#pragma unroll
        for (int nf = 0; nf < 16; ++nf) {
            o[nf][0] *= cr0; o[nf][1] *= cr0;
            o[nf][2] *= cr1; o[nf][3] *= cr1;
        }

        // O += P V : P exact fp16 hi/lo in regs, V single -> 2 MMAs/frag
#pragma unroll
        for (int ks = 0; ks < 4; ++ks) {
            uint32_t ah[4], al[4];
            split2h(s[2 * ks][0],     s[2 * ks][1],     ah[0], al[0]);
            split2h(s[2 * ks][2],     s[2 * ks][3],     ah[1], al[1]);
            split2h(s[2 * ks + 1][0], s[2 * ks + 1][1], ah[2], al[2]);
            split2h(s[2 * ks + 1][2], s[2 * ks + 1][3], ah[3], al[3]);
            const int kw = 8 * ks + tig;
#pragma unroll
            for (int nf = 0; nf < 16; ++nf) {
                const int n = (8 * nf + g) * 36;
                uint32_t bh[2];
                bh[0] = Vh[n + kw]; bh[1] = Vh[n + kw + 4];
                mma_f16(o[nf], ah, bh);
                mma_f16(o[nf], al, bh);
            }
        }
    }

    const float inv0 = 1.0f / l0;
    const float inv1 = 1.0f / l1;
    float* Og = O + hb;
    const int row0g = q0 + wid * 16 + g;
#pragma unroll
    for (int nf = 0; nf < 16; ++nf) {
        const int col = 8 * nf + 2 * tig;
        *(float2*)&Og[(size_t)row0g * DMODEL + col] =
            make_float2(o[nf][0] * inv0, o[nf][1] * inv0);
        *(float2*)&Og[(size_t)(row0g + 8) * DMODEL + col] =
            make_float2(o[nf][2] * inv1, o[nf][3] * inv1);
    }
}

// ---------------------------------------------------------------------------
extern "C" void kernel_launch(void* const* d_in, const int* in_sizes, int n_in,
                              void* d_out, int out_size)
{
    const float* x  = (const float*)d_in[0];
    const float* Wq = (const float*)d_in[1];
    const float* Wk = (const float*)d_in[2];
    const float* Wv = (const float*)d_in[3];
    const float* Wo = (const float*)d_in[4];
    float* out = (float*)d_out;

    float *Qp, *Kp, *Vp, *AOp;
    cudaGetSymbolAddress((void**)&Qp,  g_Q);
    cudaGetSymbolAddress((void**)&Kp,  g_K);
    cudaGetSymbolAddress((void**)&Vp,  g_V);
    cudaGetSymbolAddress((void**)&AOp, g_AO);

    __half *xh, *aoh, *wqh, *wkh, *wvh, *woh;
    cudaGetSymbolAddress((void**)&xh,  g_xh);
    cudaGetSymbolAddress((void**)&aoh, g_aoh);
    cudaGetSymbolAddress((void**)&wqh, g_Wqh);
    cudaGetSymbolAddress((void**)&wkh, g_Wkh);
    cudaGetSymbolAddress((void**)&wvh, g_Wvh);
    cudaGetSymbolAddress((void**)&woh, g_Woh);

    cudaFuncSetAttribute(hgemm1_kernel,
                         cudaFuncAttributeMaxDynamicSharedMemorySize, G_SMEM);
    cudaFuncSetAttribute(flash_mma_kernel,
                         cudaFuncAttributeMaxDynamicSharedMemorySize, FLASH_SMEM);

    // 1. convert inputs
    const int n2x = NTOK * DMODEL / 2;
    conv_h_kernel<<<n2x / 256, 256>>>(x, xh, n2x);
    const dim3 gt(DMODEL / 32, DMODEL / 32);
    transpose_h_kernel<<<gt, 256>>>(Wq, wqh, DMODEL, DMODEL);
    transpose_h_kernel<<<gt, 256>>>(Wk, wkh, DMODEL, DMODEL);
    transpose_h_kernel<<<gt, 256>>>(Wv, wvh, DMODEL, DMODEL);
    transpose_h_kernel<<<gt, 256>>>(Wo, woh, DMODEL, DMODEL);

    // 2. fused QKV projection
    const dim3 gqkv(3 * DMODEL / 128, NTOK / 128);   // (48, 32)
    hgemm1_kernel<<<gqkv, 256, G_SMEM>>>(xh, wqh, wkh, wvh,
                                         Qp, Kp, Vp, NTOK, DMODEL, DMODEL);

    // 3. RoPE
    const int nrope = NTOK * NH * (HDIM / 2);
    rope_kernel<<<nrope / 256, 256>>>(Qp, Kp);

    // 4. flash attention
    const dim3 gf(S_LEN / 128, NH, BATCH);           // (16, 16, 2)
    flash_mma_kernel<<<gf, 256, FLASH_SMEM>>>(Qp, Kp, Vp, AOp);

    // 5. output projection
    conv_h_kernel<<<n2x / 256, 256>>>(AOp, aoh, n2x);
    const dim3 go(DMODEL / 128, NTOK / 128);         // (16, 32)
    hgemm1_kernel<<<go, 256, G_SMEM>>>(aoh, woh, woh, woh,
                                       out, out, out, NTOK, DMODEL, DMODEL);
}

// round 8
// speedup vs baseline: 6.2746x; 1.2246x over previous
#include <cuda_runtime.h>
#include <cuda_fp16.h>
#include <math.h>
#include <stdint.h>

// Problem constants (B=2, S=2048, D=2048, H=16, HD=128)
#define S_LEN 2048
#define DMODEL 2048
#define NH 16
#define HDIM 128
#define BATCH 2
#define NTOK (BATCH * S_LEN)   // 4096

// ---------------------------------------------------------------------------
// Scratch (__device__ globals; allocation-free rule)
// ---------------------------------------------------------------------------
__device__ float g_Q[(size_t)NTOK * DMODEL];      // fp32 Q (pre-rope)
__device__ float g_K[(size_t)NTOK * DMODEL];      // fp32 K (pre-rope)

__device__ __half g_xh[(size_t)NTOK * DMODEL];    // x fp16
__device__ __half g_qh[(size_t)NTOK * DMODEL];    // roped Q fp16
__device__ __half g_kh[(size_t)NTOK * DMODEL];    // roped K fp16
__device__ __half g_vh[(size_t)NTOK * DMODEL];    // V fp16 (from GEMM)
__device__ __half g_aoh[(size_t)NTOK * DMODEL];   // attention out fp16
__device__ __half g_Wqh[(size_t)DMODEL * DMODEL];
__device__ __half g_Wkh[(size_t)DMODEL * DMODEL];
__device__ __half g_Wvh[(size_t)DMODEL * DMODEL];
__device__ __half g_Woh[(size_t)DMODEL * DMODEL];

// ---------------------------------------------------------------------------
// Helpers
// ---------------------------------------------------------------------------
__device__ __forceinline__ uint32_t packh2(float a, float b) {
    __half2 h = __floats2half2_rn(a, b);
    return *(uint32_t*)&h;
}
__device__ __forceinline__ void mma_f16(float* c, const uint32_t* a,
                                        const uint32_t* b) {
    asm volatile(
        "mma.sync.aligned.m16n8k16.row.col.f32.f16.f16.f32 "
        "{%0,%1,%2,%3}, {%4,%5,%6,%7}, {%8,%9}, {%0,%1,%2,%3};"
        : "+f"(c[0]), "+f"(c[1]), "+f"(c[2]), "+f"(c[3])
        : "r"(a[0]), "r"(a[1]), "r"(a[2]), "r"(a[3]), "r"(b[0]), "r"(b[1]));
}
__device__ __forceinline__ uint32_t smem_u32(const void* p) {
    return (uint32_t)__cvta_generic_to_shared(p);
}
__device__ __forceinline__ void cp16(uint32_t dst, const void* src) {
    asm volatile("cp.async.cg.shared.global [%0], [%1], 16;"
                 :: "r"(dst), "l"(src));
}
__device__ __forceinline__ void cp_commit() {
    asm volatile("cp.async.commit_group;");
}
template <int N>
__device__ __forceinline__ void cp_wait() {
    asm volatile("cp.async.wait_group %0;" :: "n"(N));
}
__device__ __forceinline__ void ldsm4(uint32_t& r0, uint32_t& r1,
                                      uint32_t& r2, uint32_t& r3,
                                      uint32_t addr) {
    asm volatile("ldmatrix.sync.aligned.m8n8.x4.shared.b16 {%0,%1,%2,%3}, [%4];"
                 : "=r"(r0), "=r"(r1), "=r"(r2), "=r"(r3) : "r"(addr));
}

// ---------------------------------------------------------------------------
// Conversion kernels
// ---------------------------------------------------------------------------
__global__ void __launch_bounds__(256) conv_h_kernel(
    const float* __restrict__ X, __half* __restrict__ H, int n2)
{
    int i = blockIdx.x * blockDim.x + threadIdx.x;
    if (i >= n2) return;
    float2 v = ((const float2*)X)[i];
    ((uint32_t*)H)[i] = packh2(v.x, v.y);
}

// W fp32 [K][N] -> transposed fp16 [N][K]
__global__ void __launch_bounds__(256) transpose_h_kernel(
    const float* __restrict__ W, __half* __restrict__ Th, int K, int N)
{
    __shared__ float t[32][33];
    const int k0 = blockIdx.x * 32;
    const int n0 = blockIdx.y * 32;
    const int tx = threadIdx.x & 31;
    const int ty = threadIdx.x >> 5;
#pragma unroll
    for (int i = 0; i < 4; ++i)
        t[ty + 8 * i][tx] = W[(size_t)(k0 + ty + 8 * i) * N + n0 + tx];
    __syncthreads();
#pragma unroll
    for (int i = 0; i < 4; ++i) {
        const int n = n0 + ty + 8 * i;
        Th[(size_t)n * K + k0 + tx] = __float2half_rn(t[tx][ty + 8 * i]);
    }
}

// ---------------------------------------------------------------------------
// fp16 single-term GEMM: C = A @ Bt^T, fp32 or fp16 out (fp16 when sel==2).
// Block 128x128x64, 8 warps (2m x 4n), warp 64x32, 3 cp.async stages.
// ---------------------------------------------------------------------------
#define G_STAGE 32768
#define G_SMEM (3 * G_STAGE)

__global__ void __launch_bounds__(256, 2) hgemm1_kernel(
    const __half* __restrict__ Ah,
    const __half* __restrict__ B0, const __half* __restrict__ B1,
    const __half* __restrict__ B2,
    float* __restrict__ C0, float* __restrict__ C1,
    __half* __restrict__ C2h,
    int M, int N, int K)
{
    extern __shared__ char smem[];
    const uint32_t sbase = smem_u32(smem);

    const int tid = threadIdx.x;
    const int wid = tid >> 5;
    const int lane = tid & 31;
    const int g = lane >> 2;
    const int tig = lane & 3;
    const int warp_m = wid >> 2;
    const int warp_n = wid & 3;
    const int row0 = blockIdx.y * 128;
    const int sel = blockIdx.x >> 4;
    const int col0 = (blockIdx.x & 15) * 128;

    const __half* Bt = (sel == 0) ? B0 : (sel == 1) ? B1 : B2;

    const __half* srcs[2] = { Ah + (size_t)row0 * K, Bt + (size_t)col0 * K };

    const int ntiles = K >> 6;   // 32

    auto fill = [&](int kt) {
        const uint32_t sb = sbase + (kt % 3) * G_STAGE;
        const int k0 = kt << 6;
#pragma unroll
        for (int it = 0; it < 8; ++it) {
            const int idx = tid + it * 256;          // 0..2047
            const int arr = idx >> 10;               // 0:A 1:B
            const int i = idx & 1023;
            const int r = i >> 3;
            const int ch = i & 7;
            cp16(sb + arr * 16384 + r * 128 + ((ch ^ (r & 7)) << 4),
                 srcs[arr] + (size_t)r * K + k0 + ch * 8);
        }
    };

    fill(0); cp_commit();
    fill(1); cp_commit();

    float acc[4][4][4];
#pragma unroll
    for (int mf = 0; mf < 4; ++mf)
#pragma unroll
        for (int nf = 0; nf < 4; ++nf)
#pragma unroll
            for (int r = 0; r < 4; ++r) acc[mf][nf][r] = 0.0f;

    const int a_row = (lane & 7) + ((lane >> 3) & 1) * 8;
    const int a_chs = (lane >> 4) & 1;
    const int b_row = (lane & 7) + ((lane >> 4) & 1) * 8;
    const int b_chs = (lane >> 3) & 1;

    for (int kt = 0; kt < ntiles; ++kt) {
        cp_wait<1>();
        __syncthreads();

        const uint32_t sA = sbase + (kt % 3) * G_STAGE;
        const uint32_t sB = sA + 16384;

#pragma unroll
        for (int ks = 0; ks < 4; ++ks) {
            uint32_t bh[4][2];
#pragma unroll
            for (int nb = 0; nb < 2; ++nb) {
                const int r = warp_n * 32 + nb * 16 + b_row;
                const int ch = 2 * ks + b_chs;
                ldsm4(bh[2*nb][0], bh[2*nb][1], bh[2*nb+1][0], bh[2*nb+1][1],
                      sB + r * 128 + ((ch ^ (r & 7)) << 4));
            }
#pragma unroll
            for (int mf = 0; mf < 4; ++mf) {
                const int r = warp_m * 64 + mf * 16 + a_row;
                const int ch = 2 * ks + a_chs;
                uint32_t af[4];
                ldsm4(af[0], af[1], af[2], af[3],
                      sA + r * 128 + ((ch ^ (r & 7)) << 4));
#pragma unroll
                for (int nf = 0; nf < 4; ++nf)
                    mma_f16(acc[mf][nf], af, bh[nf]);
            }
        }

        __syncthreads();
        if (kt + 2 < ntiles) fill(kt + 2);
        cp_commit();
    }

    if (sel == 2) {
        // V output: fp16 plane
#pragma unroll
        for (int mf = 0; mf < 4; ++mf) {
            const int row = row0 + warp_m * 64 + mf * 16 + g;
#pragma unroll
            for (int nf = 0; nf < 4; ++nf) {
                const int col = col0 + warp_n * 32 + nf * 8 + 2 * tig;
                *(uint32_t*)&C2h[(size_t)row * N + col] =
                    packh2(acc[mf][nf][0], acc[mf][nf][1]);
                *(uint32_t*)&C2h[(size_t)(row + 8) * N + col] =
                    packh2(acc[mf][nf][2], acc[mf][nf][3]);
            }
        }
    } else {
        float* C = (sel == 0) ? C0 : C1;
#pragma unroll
        for (int mf = 0; mf < 4; ++mf) {
            const int row = row0 + warp_m * 64 + mf * 16 + g;
#pragma unroll
            for (int nf = 0; nf < 4; ++nf) {
                const int col = col0 + warp_n * 32 + nf * 8 + 2 * tig;
                *(float2*)&C[(size_t)row * N + col] =
                    make_float2(acc[mf][nf][0], acc[mf][nf][1]);
                *(float2*)&C[(size_t)(row + 8) * N + col] =
                    make_float2(acc[mf][nf][2], acc[mf][nf][3]);
            }
        }
    }
}

// ---------------------------------------------------------------------------
// RoPE: fp32 Q/K in -> fp16 planes out.
// ---------------------------------------------------------------------------
__global__ void __launch_bounds__(256) rope_kernel(
    const float* __restrict__ Q, const float* __restrict__ K,
    __half* __restrict__ Qh, __half* __restrict__ Kh)
{
    const int idx = blockIdx.x * blockDim.x + threadIdx.x;
    const int total = NTOK * NH * (HDIM / 2);
    if (idx >= total) return;

    const int j = idx & 63;
    const int h = (idx >> 6) & (NH - 1);
    const int t = idx >> 10;
    const int pos = t & (S_LEN - 1);

    const double inv = exp(-(double)j * (9.210340371976184 / 64.0));
    const float ang = (float)((double)pos * inv);
    float sn, cs;
    sincosf(ang, &sn, &cs);

    const size_t base = (size_t)t * DMODEL + (size_t)h * HDIM + j;
    const float q1 = Q[base], q2 = Q[base + 64];
    Qh[base]      = __float2half_rn(q1 * cs - q2 * sn);
    Qh[base + 64] = __float2half_rn(q2 * cs + q1 * sn);
    const float k1 = K[base], k2 = K[base + 64];
    Kh[base]      = __float2half_rn(k1 * cs - k2 * sn);
    Kh[base + 64] = __float2half_rn(k2 * cs + k1 * sn);
}

// ---------------------------------------------------------------------------
// Flash attention, fp16 single-term (causal, tanh-cap 50, sink logit 0).
// Q, K, V as fp16 planes; QK^T = 1 MMA/frag, PV = 1 MMA/frag (P rounded fp16).
// fp32 accumulators + fp32 softmax throughout.
// CTA: 128 q-rows x kv-tiles of 64; 8 warps; warp = 16 q-rows; occ 2.
// Output written directly as fp16 (g_aoh).
// ---------------------------------------------------------------------------
#define FQ 0
#define FK (FQ + 128 * 68)
#define FV (FK + 64 * 68)
#define FLASH_WORDS (FV + 128 * 36)       // 17664 words
#define FLASH_SMEM (FLASH_WORDS * 4)      // 70656 bytes

__global__ void __launch_bounds__(256, 2) flash_mma_kernel(
    const __half* __restrict__ Q, const __half* __restrict__ K,
    const __half* __restrict__ V, __half* __restrict__ O)
{
    extern __shared__ uint32_t sf[];
    uint32_t* Qs = sf + FQ;
    uint32_t* Ks = sf + FK;
    uint32_t* Vs = sf + FV;   // transposed: [hd][kv-pair]

    const int qb = gridDim.x - 1 - blockIdx.x;
    const int h = blockIdx.y;
    const int b = blockIdx.z;
    const int tid = threadIdx.x;
    const int wid = tid >> 5;
    const int lane = tid & 31;
    const int g = lane >> 2;
    const int tig = lane & 3;
    const int q0 = qb * 128;

    const float SCALE = 0.08838834764831845f;
    const float CAP = 50.0f;
    const float INV_CAP = 1.0f / 50.0f;

    const size_t hb = (size_t)b * S_LEN * DMODEL + (size_t)h * HDIM;
    const __half* Qg = Q + hb;
    const __half* Kg = K + hb;
    const __half* Vg = V + hb;

    // Q tile fill: pure copy (128 rows x 16 uint4)
    for (int i = tid; i < 128 * 16; i += 256) {
        const int r = i >> 4;
        const int ch = i & 15;
        *(uint4*)&Qs[r * 68 + ch * 4] =
            *(const uint4*)&Qg[(size_t)(q0 + r) * DMODEL + ch * 8];
    }

    float o[16][4];
#pragma unroll
    for (int nf = 0; nf < 16; ++nf)
#pragma unroll
        for (int r = 0; r < 4; ++r) o[nf][r] = 0.0f;

    float m0 = 0.0f, m1 = 0.0f;   // sink logit 0
    float l0 = 1.0f, l1 = 1.0f;

    const int mrow0 = wid * 16 + g;
    const int kmax = 2 * qb + 1;

    for (int kb = 0; kb <= kmax; ++kb) {
        const int k0 = kb * 64;
        __syncthreads();

        // K tile fill: pure copy (64 rows x 16 uint4)
        for (int i = tid; i < 64 * 16; i += 256) {
            const int r = i >> 4;
            const int ch = i & 15;
            *(uint4*)&Ks[r * 68 + ch * 4] =
                *(const uint4*)&Kg[(size_t)(k0 + r) * DMODEL + ch * 8];
        }
        // V tile fill: transpose via byte_perm (32 pairs x 16 hd-chunks)
        for (int i = tid; i < 512; i += 256) {
            const int r = i & 31;            // kv pair
            const int c = (i >> 5) * 8;      // hd chunk base
            const uint4 a = *(const uint4*)&Vg[(size_t)(k0 + 2 * r) * DMODEL + c];
            const uint4 bb = *(const uint4*)&Vg[(size_t)(k0 + 2 * r + 1) * DMODEL + c];
            Vs[(c + 0) * 36 + r] = __byte_perm(a.x, bb.x, 0x5410);
            Vs[(c + 1) * 36 + r] = __byte_perm(a.x, bb.x, 0x7632);
            Vs[(c + 2) * 36 + r] = __byte_perm(a.y, bb.y, 0x5410);
            Vs[(c + 3) * 36 + r] = __byte_perm(a.y, bb.y, 0x7632);
            Vs[(c + 4) * 36 + r] = __byte_perm(a.z, bb.z, 0x5410);
            Vs[(c + 5) * 36 + r] = __byte_perm(a.z, bb.z, 0x7632);
            Vs[(c + 6) * 36 + r] = __byte_perm(a.w, bb.w, 0x5410);
            Vs[(c + 7) * 36 + r] = __byte_perm(a.w, bb.w, 0x7632);
        }
        __syncthreads();

        // S = Q K^T : 8 nfrags, 8 ksteps, 1 MMA each
        float s[8][4];
#pragma unroll
        for (int nf = 0; nf < 8; ++nf)
#pragma unroll
            for (int r = 0; r < 4; ++r) s[nf][r] = 0.0f;

#pragma unroll
        for (int ks = 0; ks < 8; ++ks) {
            const int kw = 8 * ks + tig;
            uint32_t ah[4];
            const int ra = (wid * 16 + g) * 68;
            const int rb = (wid * 16 + g + 8) * 68;
            ah[0] = Qs[ra + kw];     ah[1] = Qs[rb + kw];
            ah[2] = Qs[ra + kw + 4]; ah[3] = Qs[rb + kw + 4];
#pragma unroll
            for (int nf = 0; nf < 8; ++nf) {
                const int n = (8 * nf + g) * 68;
                uint32_t bh[2];
                bh[0] = Ks[n + kw]; bh[1] = Ks[n + kw + 4];
                mma_f16(s[nf], ah, bh);
            }
        }

        // scale, tanh-cap, causal mask
        const bool need_mask = (kb >= 2 * qb);
        const int grow0 = q0 + mrow0;
        const int grow1 = grow0 + 8;
#pragma unroll
        for (int nf = 0; nf < 8; ++nf) {
#pragma unroll
            for (int r = 0; r < 4; ++r) {
                float v = s[nf][r] * SCALE;
                v = CAP * tanhf(v * INV_CAP);
                if (need_mask) {
                    const int col = k0 + 8 * nf + 2 * tig + (r & 1);
                    const int row = (r < 2) ? grow0 : grow1;
                    if (col > row) v = -INFINITY;
                }
                s[nf][r] = v;
            }
        }

        // online softmax
        float rmax0 = -3.4e38f, rmax1 = -3.4e38f;
#pragma unroll
        for (int nf = 0; nf < 8; ++nf) {
            rmax0 = fmaxf(rmax0, fmaxf(s[nf][0], s[nf][1]));
            rmax1 = fmaxf(rmax1, fmaxf(s[nf][2], s[nf][3]));
        }
#pragma unroll
        for (int w = 1; w < 4; w <<= 1) {
            rmax0 = fmaxf(rmax0, __shfl_xor_sync(0xffffffffu, rmax0, w));
            rmax1 = fmaxf(rmax1, __shfl_xor_sync(0xffffffffu, rmax1, w));
        }
        const float mn0 = fmaxf(m0, rmax0);
        const float mn1 = fmaxf(m1, rmax1);
        const float cr0 = __expf(m0 - mn0);
        const float cr1 = __expf(m1 - mn1);
        m0 = mn0; m1 = mn1;

        float rs0 = 0.0f, rs1 = 0.0f;
#pragma unroll
        for (int nf = 0; nf < 8; ++nf) {
            s[nf][0] = __expf(s[nf][0] - mn0);
            s[nf][1] = __expf(s[nf][1] - mn0);
            s[nf][2] = __expf(s[nf][2] - mn1);
            s[nf][3] = __expf(s[nf][3] - mn1);
            rs0 += s[nf][0] + s[nf][1];
            rs1 += s[nf][2] + s[nf][3];
        }
#pragma unroll
        for (int w = 1; w < 4; w <<= 1) {
            rs0 += __shfl_xor_sync(0xffffffffu, rs0, w);
            rs1 += __shfl_xor_sync(0xffffffffu, rs1, w);
        }
        l0 = l0 * cr0 + rs0;
        l1 = l1 * cr1 + rs1;

#pragma unroll
        for (int nf = 0; nf < 16; ++nf) {
            o[nf][0] *= cr0; o[nf][1] *= cr0;
            o[nf][2] *= cr1; o[nf][3] *= cr1;
        }

        // O += P V : P rounded fp16, 1 MMA/frag
#pragma unroll
        for (int ks = 0; ks < 4; ++ks) {
            uint32_t ah[4];
            ah[0] = packh2(s[2 * ks][0],     s[2 * ks][1]);
            ah[1] = packh2(s[2 * ks][2],     s[2 * ks][3]);
            ah[2] = packh2(s[2 * ks + 1][0], s[2 * ks + 1][1]);
            ah[3] = packh2(s[2 * ks + 1][2], s[2 * ks + 1][3]);
            const int kw = 8 * ks + tig;
#pragma unroll
            for (int nf = 0; nf < 16; ++nf) {
                const int n = (8 * nf + g) * 36;
                uint32_t bh[2];
                bh[0] = Vs[n + kw]; bh[1] = Vs[n + kw + 4];
                mma_f16(o[nf], ah, bh);
            }
        }
    }

    // epilogue: normalize + write fp16 AO plane
    const float inv0 = 1.0f / l0;
    const float inv1 = 1.0f / l1;
    __half* Og = O + hb;
    const int row0g = q0 + wid * 16 + g;
#pragma unroll
    for (int nf = 0; nf < 16; ++nf) {
        const int col = 8 * nf + 2 * tig;
        *(uint32_t*)&Og[(size_t)row0g * DMODEL + col] =
            packh2(o[nf][0] * inv0, o[nf][1] * inv0);
        *(uint32_t*)&Og[(size_t)(row0g + 8) * DMODEL + col] =
            packh2(o[nf][2] * inv1, o[nf][3] * inv1);
    }
}

// ---------------------------------------------------------------------------
extern "C" void kernel_launch(void* const* d_in, const int* in_sizes, int n_in,
                              void* d_out, int out_size)
{
    const float* x  = (const float*)d_in[0];
    const float* Wq = (const float*)d_in[1];
    const float* Wk = (const float*)d_in[2];
    const float* Wv = (const float*)d_in[3];
    const float* Wo = (const float*)d_in[4];
    float* out = (float*)d_out;

    float *Qp, *Kp;
    cudaGetSymbolAddress((void**)&Qp, g_Q);
    cudaGetSymbolAddress((void**)&Kp, g_K);

    __half *xh, *qh, *kh, *vh, *aoh, *wqh, *wkh, *wvh, *woh;
    cudaGetSymbolAddress((void**)&xh,  g_xh);
    cudaGetSymbolAddress((void**)&qh,  g_qh);
    cudaGetSymbolAddress((void**)&kh,  g_kh);
    cudaGetSymbolAddress((void**)&vh,  g_vh);
    cudaGetSymbolAddress((void**)&aoh, g_aoh);
    cudaGetSymbolAddress((void**)&wqh, g_Wqh);
    cudaGetSymbolAddress((void**)&wkh, g_Wkh);
    cudaGetSymbolAddress((void**)&wvh, g_Wvh);
    cudaGetSymbolAddress((void**)&woh, g_Woh);

    cudaFuncSetAttribute(hgemm1_kernel,
                         cudaFuncAttributeMaxDynamicSharedMemorySize, G_SMEM);
    cudaFuncSetAttribute(flash_mma_kernel,
                         cudaFuncAttributeMaxDynamicSharedMemorySize, FLASH_SMEM);

    // 1. convert inputs
    const int n2x = NTOK * DMODEL / 2;
    conv_h_kernel<<<n2x / 256, 256>>>(x, xh, n2x);
    const dim3 gt(DMODEL / 32, DMODEL / 32);
    transpose_h_kernel<<<gt, 256>>>(Wq, wqh, DMODEL, DMODEL);
    transpose_h_kernel<<<gt, 256>>>(Wk, wkh, DMODEL, DMODEL);
    transpose_h_kernel<<<gt, 256>>>(Wv, wvh, DMODEL, DMODEL);
    transpose_h_kernel<<<gt, 256>>>(Wo, woh, DMODEL, DMODEL);

    // 2. fused QKV projection (V written directly as fp16)
    const dim3 gqkv(3 * DMODEL / 128, NTOK / 128);   // (48, 32)
    hgemm1_kernel<<<gqkv, 256, G_SMEM>>>(xh, wqh, wkh, wvh,
                                         Qp, Kp, vh, NTOK, DMODEL, DMODEL);

    // 3. RoPE: fp32 Q/K -> fp16 planes
    const int nrope = NTOK * NH * (HDIM / 2);
    rope_kernel<<<nrope / 256, 256>>>(Qp, Kp, qh, kh);

    // 4. flash attention (all-fp16 operands, fp32 softmax; writes fp16 AO)
    const dim3 gf(S_LEN / 128, NH, BATCH);           // (16, 16, 2)
    flash_mma_kernel<<<gf, 256, FLASH_SMEM>>>(qh, kh, vh, aoh);

    // 5. output projection
    const dim3 go(DMODEL / 128, NTOK / 128);         // (16, 32)
    hgemm1_kernel<<<go, 256, G_SMEM>>>(aoh, woh, woh, woh,
                                       out, out, vh, NTOK, DMODEL, DMODEL);
}

// round 9
// speedup vs baseline: 6.7890x; 1.0820x over previous
#include <cuda_runtime.h>
#include <cuda_fp16.h>
#include <math.h>
#include <stdint.h>

// Problem constants (B=2, S=2048, D=2048, H=16, HD=128)
#define S_LEN 2048
#define DMODEL 2048
#define NH 16
#define HDIM 128
#define BATCH 2
#define NTOK (BATCH * S_LEN)   // 4096

// ---------------------------------------------------------------------------
// Scratch (__device__ globals; allocation-free rule)
// ---------------------------------------------------------------------------
__device__ __half g_xh[(size_t)NTOK * DMODEL];    // x fp16
__device__ __half g_qh[(size_t)NTOK * DMODEL];    // roped Q fp16
__device__ __half g_kh[(size_t)NTOK * DMODEL];    // roped K fp16
__device__ __half g_vh[(size_t)NTOK * DMODEL];    // V fp16
__device__ __half g_aoh[(size_t)NTOK * DMODEL];   // attention out fp16
__device__ __half g_Wqh[(size_t)DMODEL * DMODEL];
__device__ __half g_Wkh[(size_t)DMODEL * DMODEL];
__device__ __half g_Wvh[(size_t)DMODEL * DMODEL];
__device__ __half g_Woh[(size_t)DMODEL * DMODEL];
__device__ float2 g_sc[(size_t)S_LEN * 64];       // (sin, cos) table

// ---------------------------------------------------------------------------
// Helpers
// ---------------------------------------------------------------------------
__device__ __forceinline__ uint32_t packh2(float a, float b) {
    __half2 h = __floats2half2_rn(a, b);
    return *(uint32_t*)&h;
}
__device__ __forceinline__ void mma_f16(float* c, const uint32_t* a,
                                        const uint32_t* b) {
    asm volatile(
        "mma.sync.aligned.m16n8k16.row.col.f32.f16.f16.f32 "
        "{%0,%1,%2,%3}, {%4,%5,%6,%7}, {%8,%9}, {%0,%1,%2,%3};"
        : "+f"(c[0]), "+f"(c[1]), "+f"(c[2]), "+f"(c[3])
        : "r"(a[0]), "r"(a[1]), "r"(a[2]), "r"(a[3]), "r"(b[0]), "r"(b[1]));
}
__device__ __forceinline__ uint32_t smem_u32(const void* p) {
    return (uint32_t)__cvta_generic_to_shared(p);
}
__device__ __forceinline__ void cp16(uint32_t dst, const void* src) {
    asm volatile("cp.async.cg.shared.global [%0], [%1], 16;"
                 :: "r"(dst), "l"(src));
}
__device__ __forceinline__ void cp_commit() {
    asm volatile("cp.async.commit_group;");
}
template <int N>
__device__ __forceinline__ void cp_wait() {
    asm volatile("cp.async.wait_group %0;" :: "n"(N));
}
__device__ __forceinline__ void ldsm4(uint32_t& r0, uint32_t& r1,
                                      uint32_t& r2, uint32_t& r3,
                                      uint32_t addr) {
    asm volatile("ldmatrix.sync.aligned.m8n8.x4.shared.b16 {%0,%1,%2,%3}, [%4];"
                 : "=r"(r0), "=r"(r1), "=r"(r2), "=r"(r3) : "r"(addr));
}
__device__ __forceinline__ void ldsm4t(uint32_t& r0, uint32_t& r1,
                                       uint32_t& r2, uint32_t& r3,
                                       uint32_t addr) {
    asm volatile("ldmatrix.sync.aligned.m8n8.x4.trans.shared.b16 {%0,%1,%2,%3}, [%4];"
                 : "=r"(r0), "=r"(r1), "=r"(r2), "=r"(r3) : "r"(addr));
}

// ---------------------------------------------------------------------------
// Small prep kernels
// ---------------------------------------------------------------------------
__global__ void __launch_bounds__(256) sincos_kernel(float2* __restrict__ T)
{
    const int idx = blockIdx.x * blockDim.x + threadIdx.x;   // 2048*64
    const int j = idx & 63;
    const int pos = idx >> 6;
    const double inv = exp(-(double)j * (9.210340371976184 / 64.0));
    const float ang = (float)((double)pos * inv);
    float sn, cs;
    sincosf(ang, &sn, &cs);
    T[idx] = make_float2(sn, cs);
}

__global__ void __launch_bounds__(256) conv_h_kernel(
    const float* __restrict__ X, __half* __restrict__ H, int n2)
{
    int i = blockIdx.x * blockDim.x + threadIdx.x;
    if (i >= n2) return;
    float2 v = ((const float2*)X)[i];
    ((uint32_t*)H)[i] = packh2(v.x, v.y);
}

// 4 weights at once (grid.z selects); W fp32 [K][N] -> fp16 [N][K]
__global__ void __launch_bounds__(256) transpose4_h_kernel(
    const float* __restrict__ W0, const float* __restrict__ W1,
    const float* __restrict__ W2, const float* __restrict__ W3,
    __half* __restrict__ T0, __half* __restrict__ T1,
    __half* __restrict__ T2, __half* __restrict__ T3, int K, int N)
{
    __shared__ float t[32][33];
    const int z = blockIdx.z;
    const float* W = (z == 0) ? W0 : (z == 1) ? W1 : (z == 2) ? W2 : W3;
    __half* Th = (z == 0) ? T0 : (z == 1) ? T1 : (z == 2) ? T2 : T3;
    const int k0 = blockIdx.x * 32;
    const int n0 = blockIdx.y * 32;
    const int tx = threadIdx.x & 31;
    const int ty = threadIdx.x >> 5;
#pragma unroll
    for (int i = 0; i < 4; ++i)
        t[ty + 8 * i][tx] = W[(size_t)(k0 + ty + 8 * i) * N + n0 + tx];
    __syncthreads();
#pragma unroll
    for (int i = 0; i < 4; ++i) {
        const int n = n0 + ty + 8 * i;
        Th[(size_t)n * K + k0 + tx] = __float2half_rn(t[tx][ty + 8 * i]);
    }
}

// ---------------------------------------------------------------------------
// fp16 GEMM, 1 MMA per output frag; epilogue variants:
//   Cf != null          : fp32 store (output projection)
//   sel == 2            : fp16 store (V)
//   sel == 0/1          : fused RoPE (smem-staged) -> fp16 Q/K planes
// Block 128x128x64, 8 warps (2m x 4n), 3 cp.async stages (96KB, occ 2).
// ---------------------------------------------------------------------------
#define G_STAGE 32768
#define G_SMEM (3 * G_STAGE)

__global__ void __launch_bounds__(256, 2) hgemm1_kernel(
    const __half* __restrict__ Ah,
    const __half* __restrict__ B0, const __half* __restrict__ B1,
    const __half* __restrict__ B2,
    __half* __restrict__ Qout, __half* __restrict__ Kout,
    __half* __restrict__ Vout, float* __restrict__ Cf,
    const float2* __restrict__ T,
    int M, int N, int K)
{
    extern __shared__ char smem[];
    const uint32_t sbase = smem_u32(smem);

    const int tid = threadIdx.x;
    const int wid = tid >> 5;
    const int lane = tid & 31;
    const int g = lane >> 2;
    const int tig = lane & 3;
    const int warp_m = wid >> 2;
    const int warp_n = wid & 3;
    const int row0 = blockIdx.y * 128;
    const int sel = blockIdx.x >> 4;
    const int col0 = (blockIdx.x & 15) * 128;

    const __half* Bt = (sel == 0) ? B0 : (sel == 1) ? B1 : B2;
    const __half* srcs[2] = { Ah + (size_t)row0 * K, Bt + (size_t)col0 * K };

    const int ntiles = K >> 6;   // 32

    auto fill = [&](int kt) {
        const uint32_t sb = sbase + (kt % 3) * G_STAGE;
        const int k0 = kt << 6;
#pragma unroll
        for (int it = 0; it < 8; ++it) {
            const int idx = tid + it * 256;          // 0..2047
            const int arr = idx >> 10;               // 0:A 1:B
            const int i = idx & 1023;
            const int r = i >> 3;
            const int ch = i & 7;
            cp16(sb + arr * 16384 + r * 128 + ((ch ^ (r & 7)) << 4),
                 srcs[arr] + (size_t)r * K + k0 + ch * 8);
        }
    };

    fill(0); cp_commit();
    fill(1); cp_commit();

    float acc[4][4][4];
#pragma unroll
    for (int mf = 0; mf < 4; ++mf)
#pragma unroll
        for (int nf = 0; nf < 4; ++nf)
#pragma unroll
            for (int r = 0; r < 4; ++r) acc[mf][nf][r] = 0.0f;

    const int a_row = (lane & 7) + ((lane >> 3) & 1) * 8;
    const int a_chs = (lane >> 4) & 1;
    const int b_row = (lane & 7) + ((lane >> 4) & 1) * 8;
    const int b_chs = (lane >> 3) & 1;

    for (int kt = 0; kt < ntiles; ++kt) {
        cp_wait<1>();
        __syncthreads();

        const uint32_t sA = sbase + (kt % 3) * G_STAGE;
        const uint32_t sB = sA + 16384;

#pragma unroll
        for (int ks = 0; ks < 4; ++ks) {
            uint32_t bh[4][2];
#pragma unroll
            for (int nb = 0; nb < 2; ++nb) {
                const int r = warp_n * 32 + nb * 16 + b_row;
                const int ch = 2 * ks + b_chs;
                ldsm4(bh[2*nb][0], bh[2*nb][1], bh[2*nb+1][0], bh[2*nb+1][1],
                      sB + r * 128 + ((ch ^ (r & 7)) << 4));
            }
#pragma unroll
            for (int mf = 0; mf < 4; ++mf) {
                const int r = warp_m * 64 + mf * 16 + a_row;
                const int ch = 2 * ks + a_chs;
                uint32_t af[4];
                ldsm4(af[0], af[1], af[2], af[3],
                      sA + r * 128 + ((ch ^ (r & 7)) << 4));
#pragma unroll
                for (int nf = 0; nf < 4; ++nf)
                    mma_f16(acc[mf][nf], af, bh[nf]);
            }
        }

        __syncthreads();
        if (kt + 2 < ntiles) fill(kt + 2);
        cp_commit();
    }

    if (Cf) {
        // fp32 epilogue (output projection)
#pragma unroll
        for (int mf = 0; mf < 4; ++mf) {
            const int row = row0 + warp_m * 64 + mf * 16 + g;
#pragma unroll
            for (int nf = 0; nf < 4; ++nf) {
                const int col = col0 + warp_n * 32 + nf * 8 + 2 * tig;
                *(float2*)&Cf[(size_t)row * N + col] =
                    make_float2(acc[mf][nf][0], acc[mf][nf][1]);
                *(float2*)&Cf[(size_t)(row + 8) * N + col] =
                    make_float2(acc[mf][nf][2], acc[mf][nf][3]);
            }
        }
    } else if (sel == 2) {
        // V: fp16 plane
#pragma unroll
        for (int mf = 0; mf < 4; ++mf) {
            const int row = row0 + warp_m * 64 + mf * 16 + g;
#pragma unroll
            for (int nf = 0; nf < 4; ++nf) {
                const int col = col0 + warp_n * 32 + nf * 8 + 2 * tig;
                *(uint32_t*)&Vout[(size_t)row * N + col] =
                    packh2(acc[mf][nf][0], acc[mf][nf][1]);
                *(uint32_t*)&Vout[(size_t)(row + 8) * N + col] =
                    packh2(acc[mf][nf][2], acc[mf][nf][3]);
            }
        }
    } else {
        // Q/K: fused RoPE via smem staging (tile = 1 head: cols 0..127)
        __syncthreads();   // all warps done reading pipeline stages
        float* st = (float*)smem;
#pragma unroll
        for (int mf = 0; mf < 4; ++mf) {
            const int r1 = warp_m * 64 + mf * 16 + g;
#pragma unroll
            for (int nf = 0; nf < 4; ++nf) {
                const int c = warp_n * 32 + nf * 8 + 2 * tig;
                st[r1 * 132 + c]           = acc[mf][nf][0];
                st[r1 * 132 + c + 1]       = acc[mf][nf][1];
                st[(r1 + 8) * 132 + c]     = acc[mf][nf][2];
                st[(r1 + 8) * 132 + c + 1] = acc[mf][nf][3];
            }
        }
        __syncthreads();
        __half* Ch = (sel == 0) ? Qout : Kout;
#pragma unroll
        for (int p = 0; p < 16; ++p) {
            const int idx = tid + 256 * p;   // 0..4095
            const int r = idx >> 5;          // 0..127
            const int j = (idx & 31) * 2;    // 0..62
            const float a0 = st[r * 132 + j];
            const float a1 = st[r * 132 + j + 1];
            const float b0 = st[r * 132 + j + 64];
            const float b1 = st[r * 132 + j + 65];
            const int pos = (row0 + r) & (S_LEN - 1);
            const float2 s0 = T[pos * 64 + j];
            const float2 s1 = T[pos * 64 + j + 1];
            const float o00 = a0 * s0.y - b0 * s0.x;
            const float o10 = b0 * s0.y + a0 * s0.x;
            const float o01 = a1 * s1.y - b1 * s1.x;
            const float o11 = b1 * s1.y + a1 * s1.x;
            const size_t rb = (size_t)(row0 + r) * N + col0;
            *(uint32_t*)&Ch[rb + j]      = packh2(o00, o01);
            *(uint32_t*)&Ch[rb + j + 64] = packh2(o10, o11);
        }
    }
}

// ---------------------------------------------------------------------------
// Flash attention, fp16 single-term (causal, tanh-cap 50, sink logit 0).
// K/V double-buffered via cp.async; V row-major + ldmatrix.trans for PV.
// CTA: 128 q-rows x kv-tiles of 64; 8 warps; warp = 16 q-rows; occ 2.
// ---------------------------------------------------------------------------
#define FQ 0
#define FK 8704                            // 2 x (64 rows x 68 words)
#define FV (FK + 2 * 64 * 68)              // 2 x (64 rows x 64 words)
#define FLASH_WORDS (FV + 2 * 64 * 64)     // 25600 words
#define FLASH_SMEM (FLASH_WORDS * 4)       // 102400 bytes

__global__ void __launch_bounds__(256, 2) flash_mma_kernel(
    const __half* __restrict__ Q, const __half* __restrict__ K,
    const __half* __restrict__ V, __half* __restrict__ O)
{
    extern __shared__ uint32_t sf[];
    uint32_t* Qs = sf + FQ;
    const uint32_t sbase = smem_u32(sf);

    const int qb = gridDim.x - 1 - blockIdx.x;
    const int h = blockIdx.y;
    const int b = blockIdx.z;
    const int tid = threadIdx.x;
    const int wid = tid >> 5;
    const int lane = tid & 31;
    const int g = lane >> 2;
    const int tig = lane & 3;
    const int q0 = qb * 128;

    const float SCALE = 0.08838834764831845f;
    const float CAP = 50.0f;
    const float INV_CAP = 1.0f / 50.0f;

    const size_t hb = (size_t)b * S_LEN * DMODEL + (size_t)h * HDIM;
    const __half* Qg = Q + hb;
    const __half* Kg = K + hb;
    const __half* Vg = V + hb;

    // K/V prefetch of tile kb into buffer kb&1 (pure cp.async copies)
    auto fillKV = [&](int kb) {
        const int k0 = kb * 64;
        const int buf = kb & 1;
        const uint32_t kb_s = sbase + (FK + buf * 64 * 68) * 4;
        const uint32_t vb_s = sbase + (FV + buf * 64 * 64) * 4;
#pragma unroll
        for (int it = 0; it < 4; ++it) {
            const int i = tid + it * 256;        // 0..1023
            const int r = i >> 4;
            const int c = i & 15;
            cp16(kb_s + r * 272 + c * 16,
                 Kg + (size_t)(k0 + r) * DMODEL + c * 8);
            cp16(vb_s + r * 256 + ((c ^ (r & 7)) << 4),
                 Vg + (size_t)(k0 + r) * DMODEL + c * 8);
        }
    };

    // Q tile fill (once)
    for (int i = tid; i < 128 * 16; i += 256) {
        const int r = i >> 4;
        const int ch = i & 15;
        *(uint4*)&Qs[r * 68 + ch * 4] =
            *(const uint4*)&Qg[(size_t)(q0 + r) * DMODEL + ch * 8];
    }

    float o[16][4];
#pragma unroll
    for (int nf = 0; nf < 16; ++nf)
#pragma unroll
        for (int r = 0; r < 4; ++r) o[nf][r] = 0.0f;

    float m0 = 0.0f, m1 = 0.0f;   // sink logit 0
    float l0 = 1.0f, l1 = 1.0f;

    const int mrow0 = wid * 16 + g;
    const int kmax = 2 * qb + 1;

    fillKV(0); cp_commit();

    for (int kb = 0; kb <= kmax; ++kb) {
        cp_wait<0>();
        __syncthreads();
        if (kb < kmax) { fillKV(kb + 1); cp_commit(); }

        const int k0 = kb * 64;
        const int buf = kb & 1;
        const uint32_t* Ks = sf + FK + buf * 64 * 68;
        const uint32_t vb_s = sbase + (FV + buf * 64 * 64) * 4;

        // S = Q K^T : 8 nfrags, 8 ksteps, 1 MMA each
        float s[8][4];
#pragma unroll
        for (int nf = 0; nf < 8; ++nf)
#pragma unroll
            for (int r = 0; r < 4; ++r) s[nf][r] = 0.0f;

#pragma unroll
        for (int ks = 0; ks < 8; ++ks) {
            const int kw = 8 * ks + tig;
            uint32_t ah[4];
            const int ra = (wid * 16 + g) * 68;
            const int rb = (wid * 16 + g + 8) * 68;
            ah[0] = Qs[ra + kw];     ah[1] = Qs[rb + kw];
            ah[2] = Qs[ra + kw + 4]; ah[3] = Qs[rb + kw + 4];
#pragma unroll
            for (int nf = 0; nf < 8; ++nf) {
                const int n = (8 * nf + g) * 68;
                uint32_t bh[2];
                bh[0] = Ks[n + kw]; bh[1] = Ks[n + kw + 4];
                mma_f16(s[nf], ah, bh);
            }
        }

        // scale, tanh-cap, causal mask
        const bool need_mask = (kb >= 2 * qb);
        const int grow0 = q0 + mrow0;
        const int grow1 = grow0 + 8;
#pragma unroll
        for (int nf = 0; nf < 8; ++nf) {
#pragma unroll
            for (int r = 0; r < 4; ++r) {
                float v = s[nf][r] * SCALE;
                v = CAP * tanhf(v * INV_CAP);
                if (need_mask) {
                    const int col = k0 + 8 * nf + 2 * tig + (r & 1);
                    const int row = (r < 2) ? grow0 : grow1;
                    if (col > row) v = -INFINITY;
                }
                s[nf][r] = v;
            }
        }

        // online softmax
        float rmax0 = -3.4e38f, rmax1 = -3.4e38f;
#pragma unroll
        for (int nf = 0; nf < 8; ++nf) {
            rmax0 = fmaxf(rmax0, fmaxf(s[nf][0], s[nf][1]));
            rmax1 = fmaxf(rmax1, fmaxf(s[nf][2], s[nf][3]));
        }
#pragma unroll
        for (int w = 1; w < 4; w <<= 1) {
            rmax0 = fmaxf(rmax0, __shfl_xor_sync(0xffffffffu, rmax0, w));
            rmax1 = fmaxf(rmax1, __shfl_xor_sync(0xffffffffu, rmax1, w));
        }
        const float mn0 = fmaxf(m0, rmax0);
        const float mn1 = fmaxf(m1, rmax1);
        const float cr0 = __expf(m0 - mn0);
        const float cr1 = __expf(m1 - mn1);
        m0 = mn0; m1 = mn1;

        float rs0 = 0.0f, rs1 = 0.0f;
#pragma unroll
        for (int nf = 0; nf < 8; ++nf) {
            s[nf][0] = __expf(s[nf][0] - mn0);
            s[nf][1] = __expf(s[nf][1] - mn0);
            s[nf][2] = __expf(s[nf][2] - mn1);
            s[nf][3] = __expf(s[nf][3] - mn1);
            rs0 += s[nf][0] + s[nf][1];
            rs1 += s[nf][2] + s[nf][3];
        }
#pragma unroll
        for (int w = 1; w < 4; w <<= 1) {
            rs0 += __shfl_xor_sync(0xffffffffu, rs0, w);
            rs1 += __shfl_xor_sync(0xffffffffu, rs1, w);
        }
        l0 = l0 * cr0 + rs0;
        l1 = l1 * cr1 + rs1;

#pragma unroll
        for (int nf = 0; nf < 16; ++nf) {
            o[nf][0] *= cr0; o[nf][1] *= cr0;
            o[nf][2] *= cr1; o[nf][3] *= cr1;
        }

        // O += P V : P rounded fp16; V fragments via ldmatrix.trans
#pragma unroll
        for (int ks = 0; ks < 4; ++ks) {
            uint32_t ah[4];
            ah[0] = packh2(s[2 * ks][0],     s[2 * ks][1]);
            ah[1] = packh2(s[2 * ks][2],     s[2 * ks][3]);
            ah[2] = packh2(s[2 * ks + 1][0], s[2 * ks + 1][1]);
            ah[3] = packh2(s[2 * ks + 1][2], s[2 * ks + 1][3]);
            const int rl = 16 * ks + (lane & 15);
#pragma unroll
            for (int nfp = 0; nfp < 8; ++nfp) {
                const int c = 2 * nfp + (lane >> 4);
                uint32_t b0a, b1a, b0b, b1b;
                ldsm4t(b0a, b1a, b0b, b1b,
                       vb_s + rl * 256 + ((c ^ (rl & 7)) << 4));
                uint32_t bA[2] = { b0a, b1a };
                uint32_t bB[2] = { b0b, b1b };
                mma_f16(o[2 * nfp],     ah, bA);
                mma_f16(o[2 * nfp + 1], ah, bB);
            }
        }
    }

    // epilogue: normalize + write fp16 AO plane
    const float inv0 = 1.0f / l0;
    const float inv1 = 1.0f / l1;
    __half* Og = O + hb;
    const int row0g = q0 + wid * 16 + g;
#pragma unroll
    for (int nf = 0; nf < 16; ++nf) {
        const int col = 8 * nf + 2 * tig;
        *(uint32_t*)&Og[(size_t)row0g * DMODEL + col] =
            packh2(o[nf][0] * inv0, o[nf][1] * inv0);
        *(uint32_t*)&Og[(size_t)(row0g + 8) * DMODEL + col] =
            packh2(o[nf][2] * inv1, o[nf][3] * inv1);
    }
}

// ---------------------------------------------------------------------------
extern "C" void kernel_launch(void* const* d_in, const int* in_sizes, int n_in,
                              void* d_out, int out_size)
{
    const float* x  = (const float*)d_in[0];
    const float* Wq = (const float*)d_in[1];
    const float* Wk = (const float*)d_in[2];
    const float* Wv = (const float*)d_in[3];
    const float* Wo = (const float*)d_in[4];
    float* out = (float*)d_out;

    __half *xh, *qh, *kh, *vh, *aoh, *wqh, *wkh, *wvh, *woh;
    float2* sc;
    cudaGetSymbolAddress((void**)&xh,  g_xh);
    cudaGetSymbolAddress((void**)&qh,  g_qh);
    cudaGetSymbolAddress((void**)&kh,  g_kh);
    cudaGetSymbolAddress((void**)&vh,  g_vh);
    cudaGetSymbolAddress((void**)&aoh, g_aoh);
    cudaGetSymbolAddress((void**)&wqh, g_Wqh);
    cudaGetSymbolAddress((void**)&wkh, g_Wkh);
    cudaGetSymbolAddress((void**)&wvh, g_Wvh);
    cudaGetSymbolAddress((void**)&woh, g_Woh);
    cudaGetSymbolAddress((void**)&sc,  g_sc);

    cudaFuncSetAttribute(hgemm1_kernel,
                         cudaFuncAttributeMaxDynamicSharedMemorySize, G_SMEM);
    cudaFuncSetAttribute(flash_mma_kernel,
                         cudaFuncAttributeMaxDynamicSharedMemorySize, FLASH_SMEM);

    // 1. prep: sincos table, x->fp16, 4 weight transposes (one launch)
    sincos_kernel<<<(S_LEN * 64) / 256, 256>>>(sc);
    const int n2x = NTOK * DMODEL / 2;
    conv_h_kernel<<<n2x / 256, 256>>>(x, xh, n2x);
    const dim3 gt(DMODEL / 32, DMODEL / 32, 4);
    transpose4_h_kernel<<<gt, 256>>>(Wq, Wk, Wv, Wo,
                                     wqh, wkh, wvh, woh, DMODEL, DMODEL);

    // 2. fused QKV projection + RoPE epilogue (Q/K/V written as fp16 planes)
    const dim3 gqkv(3 * DMODEL / 128, NTOK / 128);   // (48, 32)
    hgemm1_kernel<<<gqkv, 256, G_SMEM>>>(xh, wqh, wkh, wvh,
                                         qh, kh, vh, nullptr, sc,
                                         NTOK, DMODEL, DMODEL);

    // 3. flash attention
    const dim3 gf(S_LEN / 128, NH, BATCH);           // (16, 16, 2)
    flash_mma_kernel<<<gf, 256, FLASH_SMEM>>>(qh, kh, vh, aoh);

    // 4. output projection (fp32 out)
    const dim3 go(DMODEL / 128, NTOK / 128);         // (16, 32)
    hgemm1_kernel<<<go, 256, G_SMEM>>>(aoh, woh, woh, woh,
                                       nullptr, nullptr, nullptr, out, sc,
                                       NTOK, DMODEL, DMODEL);
}